// round 10
// baseline (speedup 1.0000x reference)
#include <cuda_runtime.h>
#include <cuda_bf16.h>
#include <math.h>
#include <stdint.h>

// Problem constants
#define B_ 8
#define T_ 2048
#define D_ 128
#define L_ 4
#define H_ 2
#define HD_ 64
#define BT_ (B_ * T_)          // 16384 rows
#define EPS_ 1e-8f

#define GP 132                 // smem pitch (floats) for 128-wide gemm tiles
#define GEMM_SMEM ((2 * 128 * GP + 128) * 4)

// ---------------------------------------------------------------------------
// Scratch buffers (allocation-free: __device__ globals)
// g_q/g_k/g_v are repurposed as bf16 hi/lo pairs (each half = BT_*128 bf16)
// ---------------------------------------------------------------------------
__device__ float g_x [BT_ * D_];
__device__ float g_u [BT_ * D_];
__device__ float g_v [BT_ * D_];   // vh | vl
__device__ float g_q [BT_ * D_];   // qh | ql
__device__ float g_k [BT_ * D_];   // kh | kl
__device__ float g_av[BT_ * D_];
__device__ float g_t [BT_ * D_];

// bf16 split-output descriptor for fused_gemm
struct BfOut {
    __nv_bfloat16* hi;
    __nv_bfloat16* lo;
    float scale;
};

// ===========================================================================
// Small helpers
// ===========================================================================
__device__ __forceinline__ uint32_t smem_u32(const void* p) {
    uint32_t a;
    asm("{ .reg .u64 t; cvta.to.shared.u64 t, %1; cvt.u32.u64 %0, t; }"
        : "=r"(a) : "l"(p));
    return a;
}

#define CP16(saddr, gptr) \
    asm volatile("cp.async.cg.shared.global [%0], [%1], 16;" \
                 :: "r"((uint32_t)(saddr)), "l"(gptr) : "memory")
#define CP_COMMIT() asm volatile("cp.async.commit_group;" ::: "memory")
#define CP_WAIT0()  asm volatile("cp.async.wait_group 0;" ::: "memory")

// bf16 hi/lo split of an fp32 value
__device__ __forceinline__ void split_bf16(float x, __nv_bfloat16& h, __nv_bfloat16& l) {
    h = __float2bfloat16(x);
    l = __float2bfloat16(x - __bfloat162float(h));
}

__device__ __forceinline__ uint32_t bf16x2_hi(float x, float y) {
    __nv_bfloat162 t = __floats2bfloat162_rn(x, y);  // .x = x in low half
    return *reinterpret_cast<uint32_t*>(&t);
}
__device__ __forceinline__ uint32_t bf16x2_lo(float x, float y) {
    float xh = __bfloat162float(__float2bfloat16(x));
    float yh = __bfloat162float(__float2bfloat16(y));
    __nv_bfloat162 t = __floats2bfloat162_rn(x - xh, y - yh);
    return *reinterpret_cast<uint32_t*>(&t);
}

// mma.sync m16n8k16 bf16 -> f32 (accumulate in place)
__device__ __forceinline__ void mma16816(float* c, const uint32_t* a,
                                         uint32_t b0, uint32_t b1) {
    asm volatile(
        "mma.sync.aligned.m16n8k16.row.col.f32.bf16.bf16.f32 "
        "{%0,%1,%2,%3}, {%4,%5,%6,%7}, {%8,%9}, {%0,%1,%2,%3};"
        : "+f"(c[0]), "+f"(c[1]), "+f"(c[2]), "+f"(c[3])
        : "r"(a[0]), "r"(a[1]), "r"(a[2]), "r"(a[3]), "r"(b0), "r"(b1));
}

// ldmatrix x2 transposed (for V B-fragments from row-major V[key][d])
__device__ __forceinline__ void ldsm_x2_trans(uint32_t& r0, uint32_t& r1, uint32_t addr) {
    asm volatile("ldmatrix.sync.aligned.m8n8.x2.trans.shared.b16 {%0,%1}, [%2];"
                 : "=r"(r0), "=r"(r1) : "r"(addr));
}

// ===========================================================================
// Elementwise RMS kernels
// ===========================================================================
__global__ void rms_kernel(const float* __restrict__ in,
                           const float* __restrict__ sc,
                           float* __restrict__ out) {
    int warp = threadIdx.x >> 5, lane = threadIdx.x & 31;
    size_t row = (size_t)blockIdx.x * 8 + warp;
    float4 v = *(const float4*)(in + row * 128 + lane * 4);
    float ss = v.x * v.x + v.y * v.y + v.z * v.z + v.w * v.w;
    #pragma unroll
    for (int o = 16; o > 0; o >>= 1) ss += __shfl_xor_sync(0xffffffffu, ss, o);
    float r = rsqrtf(ss * (1.0f / 128.0f) + EPS_);
    float4 s = *(const float4*)(sc + lane * 4);
    *(float4*)(out + row * 128 + lane * 4) =
        make_float4(v.x * r * s.x, v.y * r * s.y, v.z * r * s.z, v.w * r * s.w);
}

__global__ void embed_rms_kernel(const int* __restrict__ seq,
                                 const float* __restrict__ item,
                                 const float* __restrict__ pos,
                                 const float* __restrict__ sc,
                                 float* __restrict__ out) {
    int warp = threadIdx.x >> 5, lane = threadIdx.x & 31;
    size_t row = (size_t)blockIdx.x * 8 + warp;
    int t = (int)(row & (T_ - 1));
    int id = seq[row];
    float4 a = *(const float4*)(item + (size_t)id * 128 + lane * 4);
    float4 p = *(const float4*)(pos + (size_t)(t + 1) * 128 + lane * 4);
    float4 v = make_float4(a.x + p.x, a.y + p.y, a.z + p.z, a.w + p.w);
    float ss = v.x * v.x + v.y * v.y + v.z * v.z + v.w * v.w;
    #pragma unroll
    for (int o = 16; o > 0; o >>= 1) ss += __shfl_xor_sync(0xffffffffu, ss, o);
    float r = rsqrtf(ss * (1.0f / 128.0f) + EPS_);
    float4 s = *(const float4*)(sc + lane * 4);
    *(float4*)(out + row * 128 + lane * 4) =
        make_float4(v.x * r * s.x, v.y * r * s.y, v.z * r * s.z, v.w * r * s.w);
}

// ===========================================================================
// Fused GEMM (fp32 SIMT), 1024 threads, 2x8 outputs/thread (32 warps/SM).
// Per-weight output: fp32, or bf16 hi/lo split (scaled) when bf.hi != null.
// ===========================================================================
__global__ void __launch_bounds__(1024, 1)
fused_gemm(const float* __restrict__ A,
           const float* __restrict__ mul,
           const float* __restrict__ scvec,
           int use_rms,
           const float* __restrict__ W0, const float* __restrict__ B0, float* __restrict__ O0,
           const float* __restrict__ W1, const float* __restrict__ B1, float* __restrict__ O1,
           const float* __restrict__ W2, const float* __restrict__ B2, float* __restrict__ O2,
           const float* __restrict__ W3, const float* __restrict__ B3, float* __restrict__ O3,
           BfOut bf0, BfOut bf1, BfOut bf2, BfOut bf3,
           const float* __restrict__ res,
           int nw, int act) {
    extern __shared__ float sm[];
    float* As = sm;
    float* Ws = As + 128 * GP;
    float* rr = Ws + 128 * GP;

    int tid = threadIdx.x;
    int row0 = blockIdx.x * 128;

    for (int idx = tid; idx < 128 * 32; idx += 1024) {
        int r = idx >> 5, c4 = (idx & 31) << 2;
        *(float4*)(As + r * GP + c4) =
            *(const float4*)(A + (size_t)(row0 + r) * 128 + c4);
    }
    __syncthreads();

    if (use_rms) {
        int w = tid >> 5, lane = tid & 31;
        for (int r = w; r < 128; r += 32) {
            float4 v = *(const float4*)(As + r * GP + lane * 4);
            float ss = v.x * v.x + v.y * v.y + v.z * v.z + v.w * v.w;
            #pragma unroll
            for (int off = 16; off > 0; off >>= 1)
                ss += __shfl_xor_sync(0xffffffffu, ss, off);
            if (lane == 0) rr[r] = rsqrtf(ss * (1.0f / 128.0f) + EPS_);
        }
    } else {
        if (tid < 128) rr[tid] = 1.0f;
    }
    __syncthreads();

    if (mul) {
        for (int idx = tid; idx < 128 * 32; idx += 1024) {
            int r = idx >> 5, c4 = (idx & 31) << 2;
            float4 m = *(const float4*)(mul + (size_t)(row0 + r) * 128 + c4);
            float4 a = *(float4*)(As + r * GP + c4);
            a.x *= m.x; a.y *= m.y; a.z *= m.z; a.w *= m.w;
            *(float4*)(As + r * GP + c4) = a;
        }
    }

    int ti = tid >> 4, tj = tid & 15;   // ti: 0..63, tj: 0..15
    int r0 = ti * 2, c0 = tj * 8;

    const float* Wp[4] = {W0, W1, W2, W3};
    const float* Bp[4] = {B0, B1, B2, B3};
    float*       Op[4] = {O0, O1, O2, O3};
    BfOut        Bf[4] = {bf0, bf1, bf2, bf3};

    for (int wi = 0; wi < nw; wi++) {
        const float* W = Wp[wi];
        for (int idx = tid; idx < 128 * 32; idx += 1024) {
            int r = idx >> 5, c4 = (idx & 31) << 2;
            float s = scvec ? scvec[r] : 1.0f;
            float4 v = *(const float4*)(W + (size_t)r * 128 + c4);
            v.x *= s; v.y *= s; v.z *= s; v.w *= s;
            *(float4*)(Ws + r * GP + c4) = v;
        }
        __syncthreads();

        float acc[2][8];
        #pragma unroll
        for (int i = 0; i < 2; i++)
            #pragma unroll
            for (int j = 0; j < 8; j++) acc[i][j] = 0.0f;

        for (int k = 0; k < 128; k += 4) {
            float4 a0 = *(const float4*)(As + (r0 + 0) * GP + k);
            float4 a1 = *(const float4*)(As + (r0 + 1) * GP + k);
            #pragma unroll
            for (int kk2 = 0; kk2 < 4; kk2 += 2) {
                float4 w00 = *(const float4*)(Ws + (k + kk2) * GP + c0);
                float4 w01 = *(const float4*)(Ws + (k + kk2) * GP + c0 + 4);
                float4 w10 = *(const float4*)(Ws + (k + kk2 + 1) * GP + c0);
                float4 w11 = *(const float4*)(Ws + (k + kk2 + 1) * GP + c0 + 4);
                float a0e0 = kk2 ? a0.z : a0.x, a0e1 = kk2 ? a0.w : a0.y;
                float a1e0 = kk2 ? a1.z : a1.x, a1e1 = kk2 ? a1.w : a1.y;
                acc[0][0] += a0e0 * w00.x + a0e1 * w10.x;
                acc[0][1] += a0e0 * w00.y + a0e1 * w10.y;
                acc[0][2] += a0e0 * w00.z + a0e1 * w10.z;
                acc[0][3] += a0e0 * w00.w + a0e1 * w10.w;
                acc[0][4] += a0e0 * w01.x + a0e1 * w11.x;
                acc[0][5] += a0e0 * w01.y + a0e1 * w11.y;
                acc[0][6] += a0e0 * w01.z + a0e1 * w11.z;
                acc[0][7] += a0e0 * w01.w + a0e1 * w11.w;
                acc[1][0] += a1e0 * w00.x + a1e1 * w10.x;
                acc[1][1] += a1e0 * w00.y + a1e1 * w10.y;
                acc[1][2] += a1e0 * w00.z + a1e1 * w10.z;
                acc[1][3] += a1e0 * w00.w + a1e1 * w10.w;
                acc[1][4] += a1e0 * w01.x + a1e1 * w11.x;
                acc[1][5] += a1e0 * w01.y + a1e1 * w11.y;
                acc[1][6] += a1e0 * w01.z + a1e1 * w11.z;
                acc[1][7] += a1e0 * w01.w + a1e1 * w11.w;
            }
        }

        const float* Bv = Bp[wi];
        float* Ov = Op[wi];
        BfOut bfo = Bf[wi];
        #pragma unroll
        for (int i = 0; i < 2; i++) {
            float rri = rr[r0 + i];
            size_t grow = (size_t)(row0 + r0 + i) * 128;
            float vout[8];
            #pragma unroll
            for (int j = 0; j < 8; j++) {
                float v = acc[i][j] * rri + Bv[c0 + j];
                if (act == 1) {
                    v = v * __fdividef(1.0f, 1.0f + __expf(-v));
                } else if (act == 2) {
                    v = 0.5f * v * (1.0f + erff(v * 0.70710678118654752f));
                }
                vout[j] = v;
            }
            if (bfo.hi) {
                __nv_bfloat16 hh[8], ll[8];
                #pragma unroll
                for (int j = 0; j < 8; j++)
                    split_bf16(vout[j] * bfo.scale, hh[j], ll[j]);
                *(uint4*)(bfo.hi + grow + c0) = *(const uint4*)hh;
                *(uint4*)(bfo.lo + grow + c0) = *(const uint4*)ll;
            } else {
                if (res) {
                    #pragma unroll
                    for (int j = 0; j < 8; j++) vout[j] += res[grow + c0 + j];
                }
                *(float4*)(Ov + grow + c0)     = make_float4(vout[0], vout[1], vout[2], vout[3]);
                *(float4*)(Ov + grow + c0 + 4) = make_float4(vout[4], vout[5], vout[6], vout[7]);
            }
        }
        __syncthreads();
    }
}

// ===========================================================================
// HMMA HSTU attention, double-buffered cp.async pipeline + diag-tile skip.
// Inputs pre-converted bf16 hi/lo (Q pre-scaled). grid = (8, 16), block = 512.
// Warp pair (2p, 2p+1) owns Q-rows [16p,16p+16); warps split S-cols (sh).
// On the diagonal k-tile, only PV k-steps jpv <= pair carry unmasked data;
// both their S fragments and PV MMAs are skipped otherwise.
// ===========================================================================
#define QKP 72                 // row pitch in bf16 elements (144B -> conflict-free)
#define TILEB 18432            // one 128 x QKP bf16 tile
#define SM_QH  0
#define SM_QL  (TILEB)
#define SM_K0H (2 * TILEB)     // buf0 K hi (reused as combine scratch at end)
#define SM_K0L (3 * TILEB)
#define SM_V0H (4 * TILEB)
#define SM_V0L (5 * TILEB)
#define SM_K1H (6 * TILEB)
#define SM_K1L (7 * TILEB)
#define SM_V1H (8 * TILEB)
#define SM_V1L (9 * TILEB)
#define ATTN_SMEM (10 * TILEB)   // 184320 bytes

__global__ void __launch_bounds__(512, 1)
attn_hmma(const __nv_bfloat16* __restrict__ Qh, const __nv_bfloat16* __restrict__ Ql,
          const __nv_bfloat16* __restrict__ Kh, const __nv_bfloat16* __restrict__ Kl,
          const __nv_bfloat16* __restrict__ Vh, const __nv_bfloat16* __restrict__ Vl,
          float* __restrict__ O) {
    extern __shared__ char smc[];
    uint32_t sb = smem_u32(smc);

    int tid  = threadIdx.x;
    int warp = tid >> 5;       // 0..15
    int lane = tid & 31;
    int pair = warp >> 1;      // 0..7
    int sh   = warp & 1;       // column half
    int g    = lane >> 2;      // fragment group row 0..7
    int c2   = lane & 3;       // fragment group col 0..3
    int m0   = pair * 16;      // pair's S/O row base (0..112)

    int bh = blockIdx.y;
    int b = bh >> 1, h = bh & 1;
    int coloff = h * HD_;
    int qp = blockIdx.x;

    const uint32_t KHo[2] = {sb + SM_K0H, sb + SM_K1H};
    const uint32_t KLo[2] = {sb + SM_K0L, sb + SM_K1L};
    const uint32_t VHo[2] = {sb + SM_V0H, sb + SM_V1H};
    const uint32_t VLo[2] = {sb + SM_V0L, sb + SM_V1L};

    for (int half = 0; half < 2; half++) {
        int qt = half ? (15 - qp) : qp;
        int qbase = b * T_ + qt * 128;

        __syncthreads();   // previous q-tile consumers / scratch users done

        // ---- async copy: Q tile + K/V tile 0 ----
        for (int idx = tid; idx < 128 * 8; idx += 512) {
            int r = idx >> 3, c8 = (idx & 7) << 3;
            size_t goff = (size_t)(qbase + r) * 128 + coloff + c8;
            uint32_t soff = (uint32_t)(r * QKP + c8) * 2;
            CP16(sb + SM_QH + soff, Qh + goff);
            CP16(sb + SM_QL + soff, Ql + goff);
        }
        {
            int kbase0 = b * T_;   // kt = 0
            for (int idx = tid; idx < 128 * 8; idx += 512) {
                int r = idx >> 3, c8 = (idx & 7) << 3;
                size_t goff = (size_t)(kbase0 + r) * 128 + coloff + c8;
                uint32_t soff = (uint32_t)(r * QKP + c8) * 2;
                CP16(KHo[0] + soff, Kh + goff);
                CP16(KLo[0] + soff, Kl + goff);
                CP16(VHo[0] + soff, Vh + goff);
                CP16(VLo[0] + soff, Vl + goff);
            }
        }
        CP_COMMIT();
        CP_WAIT0();
        __syncthreads();

        // ---- A fragments for this pair's 16 Q rows (resident per warp) ----
        uint32_t Ah[4][4], Al[4][4];
        #pragma unroll
        for (int ks = 0; ks < 4; ks++) {
            uint32_t o00 = (uint32_t)((m0 + g)     * QKP + 16 * ks + 2 * c2) * 2;
            uint32_t o01 = (uint32_t)((m0 + g + 8) * QKP + 16 * ks + 2 * c2) * 2;
            Ah[ks][0] = *(const uint32_t*)(smc + SM_QH + o00);
            Ah[ks][1] = *(const uint32_t*)(smc + SM_QH + o01);
            Ah[ks][2] = *(const uint32_t*)(smc + SM_QH + o00 + 16);
            Ah[ks][3] = *(const uint32_t*)(smc + SM_QH + o01 + 16);
            Al[ks][0] = *(const uint32_t*)(smc + SM_QL + o00);
            Al[ks][1] = *(const uint32_t*)(smc + SM_QL + o01);
            Al[ks][2] = *(const uint32_t*)(smc + SM_QL + o00 + 16);
            Al[ks][3] = *(const uint32_t*)(smc + SM_QL + o01 + 16);
        }

        float Of[8][4];
        #pragma unroll
        for (int nf = 0; nf < 8; nf++)
            #pragma unroll
            for (int r = 0; r < 4; r++) Of[nf][r] = 0.0f;
        float ds0 = 0.0f, ds1 = 0.0f;

        int row0 = qt * 128 + m0 + g;       // global (in-seq) rows of this lane
        int row1 = row0 + 8;

        for (int kt = 0; kt <= qt; kt++) {
            int p = kt & 1;
            bool diag = (kt == qt);
            int jpvmax = diag ? pair : 7;   // causal skip bound (jpv index)

            // ---- prefetch tile kt+1 into the other buffer ----
            if (kt < qt) {
                int kb1 = b * T_ + (kt + 1) * 128;
                int q1 = (kt + 1) & 1;
                for (int idx = tid; idx < 128 * 8; idx += 512) {
                    int r = idx >> 3, c8 = (idx & 7) << 3;
                    size_t goff = (size_t)(kb1 + r) * 128 + coloff + c8;
                    uint32_t soff = (uint32_t)(r * QKP + c8) * 2;
                    CP16(KHo[q1] + soff, Kh + goff);
                    CP16(KLo[q1] + soff, Kl + goff);
                    CP16(VHo[q1] + soff, Vh + goff);
                    CP16(VLo[q1] + soff, Vl + goff);
                }
                CP_COMMIT();
            }

            const char* kh_s = (const char*)smc + (KHo[p] - sb);
            const char* kl_s = (const char*)smc + (KLo[p] - sb);
            uint32_t vh_b = VHo[p];
            uint32_t vl_b = VLo[p];

            // ---- this warp's S-column half ----
            uint32_t Phi[4][4], Plo[4][4];

            #pragma unroll
            for (int jj = 0; jj < 4; jj++) {
                int jpv = 4 * sh + jj;      // PV k-step index (0..7)
                if (jpv > jpvmax) continue; // fully masked on diagonal tile
                #pragma unroll
                for (int e = 0; e < 2; e++) {
                    int nfr = 2 * jpv + e;  // S n-fragment (0..15)
                    float cf[4] = {0.0f, 0.0f, 0.0f, 0.0f};
                    uint32_t kb = (uint32_t)((8 * nfr + g) * QKP + 2 * c2) * 2;
                    #pragma unroll
                    for (int ks = 0; ks < 4; ks++) {
                        uint32_t o = kb + 32 * ks;
                        uint32_t bh0 = *(const uint32_t*)(kh_s + o);
                        uint32_t bh1 = *(const uint32_t*)(kh_s + o + 16);
                        uint32_t bl0 = *(const uint32_t*)(kl_s + o);
                        uint32_t bl1 = *(const uint32_t*)(kl_s + o + 16);
                        mma16816(cf, Ah[ks], bh0, bh1);
                        mma16816(cf, Ah[ks], bl0, bl1);
                        mma16816(cf, Al[ks], bh0, bh1);
                    }
                    // gate: max(silu(a),0) with causal mask (always valid)
                    int colb = kt * 128 + 8 * nfr + 2 * c2;
                    float g0 = 0.0f, g1 = 0.0f, g2 = 0.0f, g3 = 0.0f;
                    if (cf[0] > 0.0f && colb     <= row0)
                        g0 = cf[0] * __fdividef(1.0f, 1.0f + __expf(-cf[0]));
                    if (cf[1] > 0.0f && colb + 1 <= row0)
                        g1 = cf[1] * __fdividef(1.0f, 1.0f + __expf(-cf[1]));
                    if (cf[2] > 0.0f && colb     <= row1)
                        g2 = cf[2] * __fdividef(1.0f, 1.0f + __expf(-cf[2]));
                    if (cf[3] > 0.0f && colb + 1 <= row1)
                        g3 = cf[3] * __fdividef(1.0f, 1.0f + __expf(-cf[3]));
                    ds0 += g0 + g1;
                    ds1 += g2 + g3;
                    Phi[jj][2 * e]     = bf16x2_hi(g0, g1);
                    Phi[jj][2 * e + 1] = bf16x2_hi(g2, g3);
                    Plo[jj][2 * e]     = bf16x2_lo(g0, g1);
                    Plo[jj][2 * e + 1] = bf16x2_lo(g2, g3);
                }
            }

            // O += P @ V for this warp's k-half (skipped jpv carry zero P)
            #pragma unroll
            for (int jj = 0; jj < 4; jj++) {
                int jpv = 4 * sh + jj;
                if (jpv > jpvmax) continue;
                int k0v = 16 * jpv;
                uint32_t rowa = (uint32_t)((k0v + (lane & 15)) * QKP) * 2;
                #pragma unroll
                for (int nf = 0; nf < 8; nf++) {
                    uint32_t vh0, vh1, vl0, vl1;
                    ldsm_x2_trans(vh0, vh1, vh_b + rowa + (uint32_t)(16 * nf));
                    ldsm_x2_trans(vl0, vl1, vl_b + rowa + (uint32_t)(16 * nf));
                    mma16816(Of[nf], Phi[jj], vh0, vh1);
                    mma16816(Of[nf], Phi[jj], vl0, vl1);
                    mma16816(Of[nf], Plo[jj], vh0, vh1);
                }
            }

            CP_WAIT0();        // prefetched tile resident
            __syncthreads();   // all warps done reading buffer p
        }

        // ---- quad-reduce denominators within each warp ----
        ds0 += __shfl_xor_sync(0xffffffffu, ds0, 1);
        ds0 += __shfl_xor_sync(0xffffffffu, ds0, 2);
        ds1 += __shfl_xor_sync(0xffffffffu, ds1, 1);
        ds1 += __shfl_xor_sync(0xffffffffu, ds1, 2);

        // ---- combine the two column-half partials (scratch in K0 region) ----
        float* scr = (float*)(smc + SM_K0H + pair * 4352);
        if (sh == 1) {
            float* dst = scr + lane * 32;
            #pragma unroll
            for (int nf = 0; nf < 8; nf++) {
                dst[4 * nf + 0] = Of[nf][0];
                dst[4 * nf + 1] = Of[nf][1];
                dst[4 * nf + 2] = Of[nf][2];
                dst[4 * nf + 3] = Of[nf][3];
            }
            scr[1024 + lane * 2]     = ds0;
            scr[1024 + lane * 2 + 1] = ds1;
        }
        __syncthreads();

        if (sh == 0) {
            const float* src = scr + lane * 32;
            float dt0 = ds0 + scr[1024 + lane * 2];
            float dt1 = ds1 + scr[1024 + lane * 2 + 1];
            float f0 = (dt0 > 1e-12f) ? __fdividef(1.0f, dt0 + EPS_) : 0.0f;
            float f1 = (dt1 > 1e-12f) ? __fdividef(1.0f, dt1 + EPS_) : 0.0f;

            size_t orow0 = (size_t)(qbase + m0 + g) * 128 + coloff;
            size_t orow1 = orow0 + 8 * 128;
            #pragma unroll
            for (int nf = 0; nf < 8; nf++) {
                int c = 8 * nf + 2 * c2;
                float o0 = Of[nf][0] + src[4 * nf + 0];
                float o1 = Of[nf][1] + src[4 * nf + 1];
                float o2 = Of[nf][2] + src[4 * nf + 2];
                float o3 = Of[nf][3] + src[4 * nf + 3];
                *(float2*)(O + orow0 + c) = make_float2(o0 * f0, o1 * f0);
                *(float2*)(O + orow1 + c) = make_float2(o2 * f1, o3 * f1);
            }
        }
    }
}

// ===========================================================================
// Host orchestration
// ===========================================================================
extern "C" void kernel_launch(void* const* d_in, const int* in_sizes, int n_in,
                              void* d_out, int out_size) {
    const int*   seq    = (const int*)  d_in[0];
    // d_in[1] = attn_mask (causal tril) — synthesized in-kernel
    const float* item   = (const float*)d_in[2];
    const float* pos    = (const float*)d_in[3];
    const float* emb_s  = (const float*)d_in[4];
    const float* ln1    = (const float*)d_in[5];
    const float* Uw     = (const float*)d_in[6];
    const float* Ub     = (const float*)d_in[7];
    const float* Vw     = (const float*)d_in[8];
    const float* Vb     = (const float*)d_in[9];
    const float* Qw     = (const float*)d_in[10];
    const float* Qb     = (const float*)d_in[11];
    const float* Kw     = (const float*)d_in[12];
    const float* Kb     = (const float*)d_in[13];
    const float* f2w    = (const float*)d_in[14];
    const float* f2b    = (const float*)d_in[15];
    const float* hstu   = (const float*)d_in[16];
    const float* ln2    = (const float*)d_in[17];
    const float* c1w    = (const float*)d_in[18];
    const float* c1b    = (const float*)d_in[19];
    const float* c2w    = (const float*)d_in[20];
    const float* c2b    = (const float*)d_in[21];
    const float* last_s = (const float*)d_in[22];
    float* out = (float*)d_out;

    float *x, *u, *v, *q, *k, *av, *tb;
    cudaGetSymbolAddress((void**)&x,  g_x);
    cudaGetSymbolAddress((void**)&u,  g_u);
    cudaGetSymbolAddress((void**)&v,  g_v);
    cudaGetSymbolAddress((void**)&q,  g_q);
    cudaGetSymbolAddress((void**)&k,  g_k);
    cudaGetSymbolAddress((void**)&av, g_av);
    cudaGetSymbolAddress((void**)&tb, g_t);

    __nv_bfloat16* qh = (__nv_bfloat16*)q;
    __nv_bfloat16* ql = qh + (size_t)BT_ * 128;
    __nv_bfloat16* kh = (__nv_bfloat16*)k;
    __nv_bfloat16* kl = kh + (size_t)BT_ * 128;
    __nv_bfloat16* vh = (__nv_bfloat16*)v;
    __nv_bfloat16* vl = vh + (size_t)BT_ * 128;

    BfOut bfNone = {nullptr, nullptr, 1.0f};
    BfOut bfQ = {qh, ql, 0.125f};
    BfOut bfK = {kh, kl, 1.0f};
    BfOut bfV = {vh, vl, 1.0f};

    cudaFuncSetAttribute(fused_gemm,
                         cudaFuncAttributeMaxDynamicSharedMemorySize, GEMM_SMEM);
    cudaFuncSetAttribute(attn_hmma,
                         cudaFuncAttributeMaxDynamicSharedMemorySize, ATTN_SMEM);

    dim3 gemmGrid(BT_ / 128);
    dim3 attnGrid(8, B_ * H_);

    embed_rms_kernel<<<BT_ / 8, 256>>>(seq, item, pos, emb_s, x);

    for (int l = 0; l < L_; l++) {
        size_t wo = (size_t)l * D_ * D_;
        size_t bo = (size_t)l * D_;

        if (l == 0) {
            // Layer 0: QKVU as 4 single-weight launches so ncu's 6th-launch
            // capture window lands on attn_hmma (diagnostic; costs ~13us).
            fused_gemm<<<gemmGrid, 1024, GEMM_SMEM>>>(
                x, nullptr, ln1 + bo, 1,
                Uw + wo, Ub + bo, u, nullptr, nullptr, nullptr,
                nullptr, nullptr, nullptr, nullptr, nullptr, nullptr,
                bfNone, bfNone, bfNone, bfNone, nullptr, 1, 1);
            fused_gemm<<<gemmGrid, 1024, GEMM_SMEM>>>(
                x, nullptr, ln1 + bo, 1,
                Vw + wo, Vb + bo, nullptr, nullptr, nullptr, nullptr,
                nullptr, nullptr, nullptr, nullptr, nullptr, nullptr,
                bfV, bfNone, bfNone, bfNone, nullptr, 1, 1);
            fused_gemm<<<gemmGrid, 1024, GEMM_SMEM>>>(
                x, nullptr, ln1 + bo, 1,
                Qw + wo, Qb + bo, nullptr, nullptr, nullptr, nullptr,
                nullptr, nullptr, nullptr, nullptr, nullptr, nullptr,
                bfQ, bfNone, bfNone, bfNone, nullptr, 1, 1);
            fused_gemm<<<gemmGrid, 1024, GEMM_SMEM>>>(
                x, nullptr, ln1 + bo, 1,
                Kw + wo, Kb + bo, nullptr, nullptr, nullptr, nullptr,
                nullptr, nullptr, nullptr, nullptr, nullptr, nullptr,
                bfK, bfNone, bfNone, bfNone, nullptr, 1, 1);
        } else {
            fused_gemm<<<gemmGrid, 1024, GEMM_SMEM>>>(
                x, nullptr, ln1 + bo, 1,
                Uw + wo, Ub + bo, u,
                Vw + wo, Vb + bo, nullptr,
                Qw + wo, Qb + bo, nullptr,
                Kw + wo, Kb + bo, nullptr,
                bfNone, bfV, bfQ, bfK,
                nullptr, 4, 1);
        }

        attn_hmma<<<attnGrid, 512, ATTN_SMEM>>>(qh, ql, kh, kl, vh, vl, av);

        fused_gemm<<<gemmGrid, 1024, GEMM_SMEM>>>(
            av, u, hstu + bo, 1,
            f2w + wo, f2b + bo, x,
            nullptr, nullptr, nullptr,
            nullptr, nullptr, nullptr,
            nullptr, nullptr, nullptr,
            bfNone, bfNone, bfNone, bfNone,
            x, 1, 0);

        fused_gemm<<<gemmGrid, 1024, GEMM_SMEM>>>(
            x, nullptr, ln2 + bo, 1,
            c1w + wo, c1b + bo, tb,
            nullptr, nullptr, nullptr,
            nullptr, nullptr, nullptr,
            nullptr, nullptr, nullptr,
            bfNone, bfNone, bfNone, bfNone,
            nullptr, 1, 2);

        fused_gemm<<<gemmGrid, 1024, GEMM_SMEM>>>(
            tb, nullptr, nullptr, 0,
            c2w + wo, c2b + bo, x,
            nullptr, nullptr, nullptr,
            nullptr, nullptr, nullptr,
            nullptr, nullptr, nullptr,
            bfNone, bfNone, bfNone, bfNone,
            x, 1, 0);
    }

    rms_kernel<<<BT_ / 8, 256>>>(x, last_s, out);
}

// round 11
// speedup vs baseline: 1.4031x; 1.4031x over previous
#include <cuda_runtime.h>
#include <cuda_bf16.h>
#include <math.h>
#include <stdint.h>

// Problem constants
#define B_ 8
#define T_ 2048
#define D_ 128
#define L_ 4
#define H_ 2
#define HD_ 64
#define BT_ (B_ * T_)          // 16384 rows
#define EPS_ 1e-8f

#define GP 132                 // smem pitch (floats) for 128-wide gemm tiles
#define GEMM_SMEM ((2 * 128 * GP + 128) * 4)

// ---------------------------------------------------------------------------
// Scratch buffers (allocation-free: __device__ globals)
// g_q/g_k/g_v are repurposed as bf16 hi/lo pairs (each half = BT_*128 bf16)
// ---------------------------------------------------------------------------
__device__ float g_x [BT_ * D_];
__device__ float g_u [BT_ * D_];
__device__ float g_v [BT_ * D_];   // vh | vl
__device__ float g_q [BT_ * D_];   // qh | ql (ql written but unused now)
__device__ float g_k [BT_ * D_];   // kh | kl
__device__ float g_av[BT_ * D_];
__device__ float g_t [BT_ * D_];

// bf16 split-output descriptor for fused_gemm
struct BfOut {
    __nv_bfloat16* hi;
    __nv_bfloat16* lo;
    float scale;
};

// ===========================================================================
// Small helpers
// ===========================================================================
__device__ __forceinline__ uint32_t smem_u32(const void* p) {
    uint32_t a;
    asm("{ .reg .u64 t; cvta.to.shared.u64 t, %1; cvt.u32.u64 %0, t; }"
        : "=r"(a) : "l"(p));
    return a;
}

#define CP16(saddr, gptr) \
    asm volatile("cp.async.cg.shared.global [%0], [%1], 16;" \
                 :: "r"((uint32_t)(saddr)), "l"(gptr) : "memory")
#define CP_COMMIT() asm volatile("cp.async.commit_group;" ::: "memory")
#define CP_WAIT0()  asm volatile("cp.async.wait_group 0;" ::: "memory")

// bf16 hi/lo split of an fp32 value
__device__ __forceinline__ void split_bf16(float x, __nv_bfloat16& h, __nv_bfloat16& l) {
    h = __float2bfloat16(x);
    l = __float2bfloat16(x - __bfloat162float(h));
}

__device__ __forceinline__ uint32_t bf16x2_hi(float x, float y) {
    __nv_bfloat162 t = __floats2bfloat162_rn(x, y);  // .x = x in low half
    return *reinterpret_cast<uint32_t*>(&t);
}
__device__ __forceinline__ uint32_t bf16x2_lo(float x, float y) {
    float xh = __bfloat162float(__float2bfloat16(x));
    float yh = __bfloat162float(__float2bfloat16(y));
    __nv_bfloat162 t = __floats2bfloat162_rn(x - xh, y - yh);
    return *reinterpret_cast<uint32_t*>(&t);
}

// mma.sync m16n8k16 bf16 -> f32 (accumulate in place)
__device__ __forceinline__ void mma16816(float* c, const uint32_t* a,
                                         uint32_t b0, uint32_t b1) {
    asm volatile(
        "mma.sync.aligned.m16n8k16.row.col.f32.bf16.bf16.f32 "
        "{%0,%1,%2,%3}, {%4,%5,%6,%7}, {%8,%9}, {%0,%1,%2,%3};"
        : "+f"(c[0]), "+f"(c[1]), "+f"(c[2]), "+f"(c[3])
        : "r"(a[0]), "r"(a[1]), "r"(a[2]), "r"(a[3]), "r"(b0), "r"(b1));
}

// ldmatrix x2 transposed (for V B-fragments from row-major V[key][d])
__device__ __forceinline__ void ldsm_x2_trans(uint32_t& r0, uint32_t& r1, uint32_t addr) {
    asm volatile("ldmatrix.sync.aligned.m8n8.x2.trans.shared.b16 {%0,%1}, [%2];"
                 : "=r"(r0), "=r"(r1) : "r"(addr));
}

// ===========================================================================
// Elementwise RMS kernels
// ===========================================================================
__global__ void rms_kernel(const float* __restrict__ in,
                           const float* __restrict__ sc,
                           float* __restrict__ out) {
    int warp = threadIdx.x >> 5, lane = threadIdx.x & 31;
    size_t row = (size_t)blockIdx.x * 8 + warp;
    float4 v = *(const float4*)(in + row * 128 + lane * 4);
    float ss = v.x * v.x + v.y * v.y + v.z * v.z + v.w * v.w;
    #pragma unroll
    for (int o = 16; o > 0; o >>= 1) ss += __shfl_xor_sync(0xffffffffu, ss, o);
    float r = rsqrtf(ss * (1.0f / 128.0f) + EPS_);
    float4 s = *(const float4*)(sc + lane * 4);
    *(float4*)(out + row * 128 + lane * 4) =
        make_float4(v.x * r * s.x, v.y * r * s.y, v.z * r * s.z, v.w * r * s.w);
}

__global__ void embed_rms_kernel(const int* __restrict__ seq,
                                 const float* __restrict__ item,
                                 const float* __restrict__ pos,
                                 const float* __restrict__ sc,
                                 float* __restrict__ out) {
    int warp = threadIdx.x >> 5, lane = threadIdx.x & 31;
    size_t row = (size_t)blockIdx.x * 8 + warp;
    int t = (int)(row & (T_ - 1));
    int id = seq[row];
    float4 a = *(const float4*)(item + (size_t)id * 128 + lane * 4);
    float4 p = *(const float4*)(pos + (size_t)(t + 1) * 128 + lane * 4);
    float4 v = make_float4(a.x + p.x, a.y + p.y, a.z + p.z, a.w + p.w);
    float ss = v.x * v.x + v.y * v.y + v.z * v.z + v.w * v.w;
    #pragma unroll
    for (int o = 16; o > 0; o >>= 1) ss += __shfl_xor_sync(0xffffffffu, ss, o);
    float r = rsqrtf(ss * (1.0f / 128.0f) + EPS_);
    float4 s = *(const float4*)(sc + lane * 4);
    *(float4*)(out + row * 128 + lane * 4) =
        make_float4(v.x * r * s.x, v.y * r * s.y, v.z * r * s.z, v.w * r * s.w);
}

// ===========================================================================
// Fused GEMM (fp32 SIMT), 512 threads, 4x8 outputs/thread (round-9 version:
// at the FFMA roofline). Per-weight output: fp32, or bf16 hi/lo (scaled).
// ===========================================================================
__global__ void __launch_bounds__(512)
fused_gemm(const float* __restrict__ A,
           const float* __restrict__ mul,
           const float* __restrict__ scvec,
           int use_rms,
           const float* __restrict__ W0, const float* __restrict__ B0, float* __restrict__ O0,
           const float* __restrict__ W1, const float* __restrict__ B1, float* __restrict__ O1,
           const float* __restrict__ W2, const float* __restrict__ B2, float* __restrict__ O2,
           const float* __restrict__ W3, const float* __restrict__ B3, float* __restrict__ O3,
           BfOut bf0, BfOut bf1, BfOut bf2, BfOut bf3,
           const float* __restrict__ res,
           int nw, int act) {
    extern __shared__ float sm[];
    float* As = sm;
    float* Ws = As + 128 * GP;
    float* rr = Ws + 128 * GP;

    int tid = threadIdx.x;
    int row0 = blockIdx.x * 128;

    for (int idx = tid; idx < 128 * 32; idx += 512) {
        int r = idx >> 5, c4 = (idx & 31) << 2;
        *(float4*)(As + r * GP + c4) =
            *(const float4*)(A + (size_t)(row0 + r) * 128 + c4);
    }
    __syncthreads();

    if (use_rms) {
        int w = tid >> 5, lane = tid & 31;
        for (int r = w; r < 128; r += 16) {
            float4 v = *(const float4*)(As + r * GP + lane * 4);
            float ss = v.x * v.x + v.y * v.y + v.z * v.z + v.w * v.w;
            #pragma unroll
            for (int off = 16; off > 0; off >>= 1)
                ss += __shfl_xor_sync(0xffffffffu, ss, off);
            if (lane == 0) rr[r] = rsqrtf(ss * (1.0f / 128.0f) + EPS_);
        }
    } else {
        if (tid < 128) rr[tid] = 1.0f;
    }
    __syncthreads();

    if (mul) {
        for (int idx = tid; idx < 128 * 32; idx += 512) {
            int r = idx >> 5, c4 = (idx & 31) << 2;
            float4 m = *(const float4*)(mul + (size_t)(row0 + r) * 128 + c4);
            float4 a = *(float4*)(As + r * GP + c4);
            a.x *= m.x; a.y *= m.y; a.z *= m.z; a.w *= m.w;
            *(float4*)(As + r * GP + c4) = a;
        }
    }

    int ti = tid >> 4, tj = tid & 15;
    int r0 = ti * 4, c0 = tj * 8;

    const float* Wp[4] = {W0, W1, W2, W3};
    const float* Bp[4] = {B0, B1, B2, B3};
    float*       Op[4] = {O0, O1, O2, O3};
    BfOut        Bf[4] = {bf0, bf1, bf2, bf3};

    for (int wi = 0; wi < nw; wi++) {
        const float* W = Wp[wi];
        for (int idx = tid; idx < 128 * 32; idx += 512) {
            int r = idx >> 5, c4 = (idx & 31) << 2;
            float s = scvec ? scvec[r] : 1.0f;
            float4 v = *(const float4*)(W + (size_t)r * 128 + c4);
            v.x *= s; v.y *= s; v.z *= s; v.w *= s;
            *(float4*)(Ws + r * GP + c4) = v;
        }
        __syncthreads();

        float acc[4][8];
        #pragma unroll
        for (int i = 0; i < 4; i++)
            #pragma unroll
            for (int j = 0; j < 8; j++) acc[i][j] = 0.0f;

        for (int k = 0; k < 128; k += 4) {
            float4 w0[4], w1[4];
            #pragma unroll
            for (int kk = 0; kk < 4; kk++) {
                w0[kk] = *(const float4*)(Ws + (k + kk) * GP + c0);
                w1[kk] = *(const float4*)(Ws + (k + kk) * GP + c0 + 4);
            }
            #pragma unroll
            for (int i = 0; i < 4; i++) {
                float4 a = *(const float4*)(As + (r0 + i) * GP + k);
                acc[i][0] += a.x * w0[0].x + a.y * w0[1].x + a.z * w0[2].x + a.w * w0[3].x;
                acc[i][1] += a.x * w0[0].y + a.y * w0[1].y + a.z * w0[2].y + a.w * w0[3].y;
                acc[i][2] += a.x * w0[0].z + a.y * w0[1].z + a.z * w0[2].z + a.w * w0[3].z;
                acc[i][3] += a.x * w0[0].w + a.y * w0[1].w + a.z * w0[2].w + a.w * w0[3].w;
                acc[i][4] += a.x * w1[0].x + a.y * w1[1].x + a.z * w1[2].x + a.w * w1[3].x;
                acc[i][5] += a.x * w1[0].y + a.y * w1[1].y + a.z * w1[2].y + a.w * w1[3].y;
                acc[i][6] += a.x * w1[0].z + a.y * w1[1].z + a.z * w1[2].z + a.w * w1[3].z;
                acc[i][7] += a.x * w1[0].w + a.y * w1[1].w + a.z * w1[2].w + a.w * w1[3].w;
            }
        }

        const float* Bv = Bp[wi];
        float* Ov = Op[wi];
        BfOut bfo = Bf[wi];
        #pragma unroll
        for (int i = 0; i < 4; i++) {
            float rri = rr[r0 + i];
            size_t grow = (size_t)(row0 + r0 + i) * 128;
            float vout[8];
            #pragma unroll
            for (int j = 0; j < 8; j++) {
                float v = acc[i][j] * rri + Bv[c0 + j];
                if (act == 1) {
                    v = v * __fdividef(1.0f, 1.0f + __expf(-v));
                } else if (act == 2) {
                    v = 0.5f * v * (1.0f + erff(v * 0.70710678118654752f));
                }
                vout[j] = v;
            }
            if (bfo.hi) {
                __nv_bfloat16 hh[8], ll[8];
                #pragma unroll
                for (int j = 0; j < 8; j++)
                    split_bf16(vout[j] * bfo.scale, hh[j], ll[j]);
                *(uint4*)(bfo.hi + grow + c0) = *(const uint4*)hh;
                *(uint4*)(bfo.lo + grow + c0) = *(const uint4*)ll;
            } else {
                if (res) {
                    #pragma unroll
                    for (int j = 0; j < 8; j++) vout[j] += res[grow + c0 + j];
                }
                *(float4*)(Ov + grow + c0)     = make_float4(vout[0], vout[1], vout[2], vout[3]);
                *(float4*)(Ov + grow + c0 + 4) = make_float4(vout[4], vout[5], vout[6], vout[7]);
            }
        }
        __syncthreads();
    }
}

// ===========================================================================
// HMMA HSTU attention, double-buffered cp.async pipeline.
// QK uses 2-pass hi/lo split (Qh·Kh + Qh·Kl); PV keeps 3-pass.
// grid = (8, 16), block = 512. Warp pair (2p, 2p+1) owns Q-rows [16p,16p+16);
// the two warps split the 128 S-columns / PV k-range (sh = warp&1).
// Block handles q-tiles qp and 15-qp (causal load balancing).
// ===========================================================================
#define QKP 72                 // row pitch in bf16 elements (144B -> conflict-free)
#define TILEB 18432            // one 128 x QKP bf16 tile
#define SM_QH  0
#define SM_K0H (1 * TILEB)     // buf0 K hi (reused as combine scratch at end)
#define SM_K0L (2 * TILEB)
#define SM_V0H (3 * TILEB)
#define SM_V0L (4 * TILEB)
#define SM_K1H (5 * TILEB)
#define SM_K1L (6 * TILEB)
#define SM_V1H (7 * TILEB)
#define SM_V1L (8 * TILEB)
#define ATTN_SMEM (9 * TILEB)   // 165888 bytes

__global__ void __launch_bounds__(512, 1)
attn_hmma(const __nv_bfloat16* __restrict__ Qh,
          const __nv_bfloat16* __restrict__ Kh, const __nv_bfloat16* __restrict__ Kl,
          const __nv_bfloat16* __restrict__ Vh, const __nv_bfloat16* __restrict__ Vl,
          float* __restrict__ O) {
    extern __shared__ char smc[];
    uint32_t sb = smem_u32(smc);

    int tid  = threadIdx.x;
    int warp = tid >> 5;       // 0..15
    int lane = tid & 31;
    int pair = warp >> 1;      // 0..7
    int sh   = warp & 1;       // column half
    int g    = lane >> 2;      // fragment group row 0..7
    int c2   = lane & 3;       // fragment group col 0..3
    int m0   = pair * 16;      // pair's S/O row base (0..112)

    int bh = blockIdx.y;
    int b = bh >> 1, h = bh & 1;
    int coloff = h * HD_;
    int qp = blockIdx.x;

    const uint32_t KHo[2] = {sb + SM_K0H, sb + SM_K1H};
    const uint32_t KLo[2] = {sb + SM_K0L, sb + SM_K1L};
    const uint32_t VHo[2] = {sb + SM_V0H, sb + SM_V1H};
    const uint32_t VLo[2] = {sb + SM_V0L, sb + SM_V1L};

    for (int half = 0; half < 2; half++) {
        int qt = half ? (15 - qp) : qp;
        int qbase = b * T_ + qt * 128;

        __syncthreads();   // previous q-tile consumers / scratch users done

        // ---- async copy: Q tile (hi only) + K/V tile 0 ----
        for (int idx = tid; idx < 128 * 8; idx += 512) {
            int r = idx >> 3, c8 = (idx & 7) << 3;
            size_t goff = (size_t)(qbase + r) * 128 + coloff + c8;
            uint32_t soff = (uint32_t)(r * QKP + c8) * 2;
            CP16(sb + SM_QH + soff, Qh + goff);
        }
        {
            int kbase0 = b * T_;   // kt = 0
            for (int idx = tid; idx < 128 * 8; idx += 512) {
                int r = idx >> 3, c8 = (idx & 7) << 3;
                size_t goff = (size_t)(kbase0 + r) * 128 + coloff + c8;
                uint32_t soff = (uint32_t)(r * QKP + c8) * 2;
                CP16(KHo[0] + soff, Kh + goff);
                CP16(KLo[0] + soff, Kl + goff);
                CP16(VHo[0] + soff, Vh + goff);
                CP16(VLo[0] + soff, Vl + goff);
            }
        }
        CP_COMMIT();
        CP_WAIT0();
        __syncthreads();

        // ---- A fragments (hi only) for this pair's 16 Q rows ----
        uint32_t Ah[4][4];
        #pragma unroll
        for (int ks = 0; ks < 4; ks++) {
            uint32_t o00 = (uint32_t)((m0 + g)     * QKP + 16 * ks + 2 * c2) * 2;
            uint32_t o01 = (uint32_t)((m0 + g + 8) * QKP + 16 * ks + 2 * c2) * 2;
            Ah[ks][0] = *(const uint32_t*)(smc + SM_QH + o00);
            Ah[ks][1] = *(const uint32_t*)(smc + SM_QH + o01);
            Ah[ks][2] = *(const uint32_t*)(smc + SM_QH + o00 + 16);
            Ah[ks][3] = *(const uint32_t*)(smc + SM_QH + o01 + 16);
        }

        float Of[8][4];
        #pragma unroll
        for (int nf = 0; nf < 8; nf++)
            #pragma unroll
            for (int r = 0; r < 4; r++) Of[nf][r] = 0.0f;
        float ds0 = 0.0f, ds1 = 0.0f;

        int row0 = qt * 128 + m0 + g;       // global (in-seq) rows of this lane
        int row1 = row0 + 8;

        for (int kt = 0; kt <= qt; kt++) {
            int p = kt & 1;

            // ---- prefetch tile kt+1 into the other buffer ----
            if (kt < qt) {
                int kb1 = b * T_ + (kt + 1) * 128;
                int q1 = (kt + 1) & 1;
                for (int idx = tid; idx < 128 * 8; idx += 512) {
                    int r = idx >> 3, c8 = (idx & 7) << 3;
                    size_t goff = (size_t)(kb1 + r) * 128 + coloff + c8;
                    uint32_t soff = (uint32_t)(r * QKP + c8) * 2;
                    CP16(KHo[q1] + soff, Kh + goff);
                    CP16(KLo[q1] + soff, Kl + goff);
                    CP16(VHo[q1] + soff, Vh + goff);
                    CP16(VLo[q1] + soff, Vl + goff);
                }
                CP_COMMIT();
            }

            const char* kh_s = (const char*)smc + (KHo[p] - sb);
            const char* kl_s = (const char*)smc + (KLo[p] - sb);
            uint32_t vh_b = VHo[p];
            uint32_t vl_b = VLo[p];

            // ---- this warp's S-column half ----
            uint32_t Phi[4][4], Plo[4][4];

            // S = Q @ K^T (2-pass: Qh·Kh + Qh·Kl), gate, pack P frags
            #pragma unroll
            for (int jj = 0; jj < 4; jj++) {
                int jpv = 4 * sh + jj;      // PV k-step index (0..7)
                #pragma unroll
                for (int e = 0; e < 2; e++) {
                    int nfr = 2 * jpv + e;  // S n-fragment (0..15)
                    float cf[4] = {0.0f, 0.0f, 0.0f, 0.0f};
                    uint32_t kb = (uint32_t)((8 * nfr + g) * QKP + 2 * c2) * 2;
                    #pragma unroll
                    for (int ks = 0; ks < 4; ks++) {
                        uint32_t o = kb + 32 * ks;
                        uint32_t bh0 = *(const uint32_t*)(kh_s + o);
                        uint32_t bh1 = *(const uint32_t*)(kh_s + o + 16);
                        uint32_t bl0 = *(const uint32_t*)(kl_s + o);
                        uint32_t bl1 = *(const uint32_t*)(kl_s + o + 16);
                        mma16816(cf, Ah[ks], bh0, bh1);
                        mma16816(cf, Ah[ks], bl0, bl1);
                    }
                    // gate: max(silu(a),0) with causal mask (always valid)
                    int colb = kt * 128 + 8 * nfr + 2 * c2;
                    float g0 = 0.0f, g1 = 0.0f, g2 = 0.0f, g3 = 0.0f;
                    if (cf[0] > 0.0f && colb     <= row0)
                        g0 = cf[0] * __fdividef(1.0f, 1.0f + __expf(-cf[0]));
                    if (cf[1] > 0.0f && colb + 1 <= row0)
                        g1 = cf[1] * __fdividef(1.0f, 1.0f + __expf(-cf[1]));
                    if (cf[2] > 0.0f && colb     <= row1)
                        g2 = cf[2] * __fdividef(1.0f, 1.0f + __expf(-cf[2]));
                    if (cf[3] > 0.0f && colb + 1 <= row1)
                        g3 = cf[3] * __fdividef(1.0f, 1.0f + __expf(-cf[3]));
                    ds0 += g0 + g1;
                    ds1 += g2 + g3;
                    Phi[jj][2 * e]     = bf16x2_hi(g0, g1);
                    Phi[jj][2 * e + 1] = bf16x2_hi(g2, g3);
                    Plo[jj][2 * e]     = bf16x2_lo(g0, g1);
                    Plo[jj][2 * e + 1] = bf16x2_lo(g2, g3);
                }
            }

            // O += P @ V for this warp's k-half (3-pass)
            #pragma unroll
            for (int jj = 0; jj < 4; jj++) {
                int k0v = 16 * (4 * sh + jj);
                uint32_t rowa = (uint32_t)((k0v + (lane & 15)) * QKP) * 2;
                #pragma unroll
                for (int nf = 0; nf < 8; nf++) {
                    uint32_t vh0, vh1, vl0, vl1;
                    ldsm_x2_trans(vh0, vh1, vh_b + rowa + (uint32_t)(16 * nf));
                    ldsm_x2_trans(vl0, vl1, vl_b + rowa + (uint32_t)(16 * nf));
                    mma16816(Of[nf], Phi[jj], vh0, vh1);
                    mma16816(Of[nf], Phi[jj], vl0, vl1);
                    mma16816(Of[nf], Plo[jj], vh0, vh1);
                }
            }

            CP_WAIT0();        // prefetched tile resident
            __syncthreads();   // all warps done reading buffer p
        }

        // ---- quad-reduce denominators within each warp ----
        ds0 += __shfl_xor_sync(0xffffffffu, ds0, 1);
        ds0 += __shfl_xor_sync(0xffffffffu, ds0, 2);
        ds1 += __shfl_xor_sync(0xffffffffu, ds1, 1);
        ds1 += __shfl_xor_sync(0xffffffffu, ds1, 2);

        // ---- combine the two column-half partials (scratch in K0 region) ----
        float* scr = (float*)(smc + SM_K0H + pair * 4352);
        if (sh == 1) {
            float* dst = scr + lane * 32;
            #pragma unroll
            for (int nf = 0; nf < 8; nf++) {
                dst[4 * nf + 0] = Of[nf][0];
                dst[4 * nf + 1] = Of[nf][1];
                dst[4 * nf + 2] = Of[nf][2];
                dst[4 * nf + 3] = Of[nf][3];
            }
            scr[1024 + lane * 2]     = ds0;
            scr[1024 + lane * 2 + 1] = ds1;
        }
        __syncthreads();

        if (sh == 0) {
            const float* src = scr + lane * 32;
            float dt0 = ds0 + scr[1024 + lane * 2];
            float dt1 = ds1 + scr[1024 + lane * 2 + 1];
            float f0 = (dt0 > 1e-12f) ? __fdividef(1.0f, dt0 + EPS_) : 0.0f;
            float f1 = (dt1 > 1e-12f) ? __fdividef(1.0f, dt1 + EPS_) : 0.0f;

            size_t orow0 = (size_t)(qbase + m0 + g) * 128 + coloff;
            size_t orow1 = orow0 + 8 * 128;
            #pragma unroll
            for (int nf = 0; nf < 8; nf++) {
                int c = 8 * nf + 2 * c2;
                float o0 = Of[nf][0] + src[4 * nf + 0];
                float o1 = Of[nf][1] + src[4 * nf + 1];
                float o2 = Of[nf][2] + src[4 * nf + 2];
                float o3 = Of[nf][3] + src[4 * nf + 3];
                *(float2*)(O + orow0 + c) = make_float2(o0 * f0, o1 * f0);
                *(float2*)(O + orow1 + c) = make_float2(o2 * f1, o3 * f1);
            }
        }
    }
}

// ===========================================================================
// Host orchestration
// ===========================================================================
extern "C" void kernel_launch(void* const* d_in, const int* in_sizes, int n_in,
                              void* d_out, int out_size) {
    const int*   seq    = (const int*)  d_in[0];
    // d_in[1] = attn_mask (causal tril) — synthesized in-kernel
    const float* item   = (const float*)d_in[2];
    const float* pos    = (const float*)d_in[3];
    const float* emb_s  = (const float*)d_in[4];
    const float* ln1    = (const float*)d_in[5];
    const float* Uw     = (const float*)d_in[6];
    const float* Ub     = (const float*)d_in[7];
    const float* Vw     = (const float*)d_in[8];
    const float* Vb     = (const float*)d_in[9];
    const float* Qw     = (const float*)d_in[10];
    const float* Qb     = (const float*)d_in[11];
    const float* Kw     = (const float*)d_in[12];
    const float* Kb     = (const float*)d_in[13];
    const float* f2w    = (const float*)d_in[14];
    const float* f2b    = (const float*)d_in[15];
    const float* hstu   = (const float*)d_in[16];
    const float* ln2    = (const float*)d_in[17];
    const float* c1w    = (const float*)d_in[18];
    const float* c1b    = (const float*)d_in[19];
    const float* c2w    = (const float*)d_in[20];
    const float* c2b    = (const float*)d_in[21];
    const float* last_s = (const float*)d_in[22];
    float* out = (float*)d_out;

    float *x, *u, *v, *q, *k, *av, *tb;
    cudaGetSymbolAddress((void**)&x,  g_x);
    cudaGetSymbolAddress((void**)&u,  g_u);
    cudaGetSymbolAddress((void**)&v,  g_v);
    cudaGetSymbolAddress((void**)&q,  g_q);
    cudaGetSymbolAddress((void**)&k,  g_k);
    cudaGetSymbolAddress((void**)&av, g_av);
    cudaGetSymbolAddress((void**)&tb, g_t);

    __nv_bfloat16* qh = (__nv_bfloat16*)q;
    __nv_bfloat16* ql = qh + (size_t)BT_ * 128;
    __nv_bfloat16* kh = (__nv_bfloat16*)k;
    __nv_bfloat16* kl = kh + (size_t)BT_ * 128;
    __nv_bfloat16* vh = (__nv_bfloat16*)v;
    __nv_bfloat16* vl = vh + (size_t)BT_ * 128;

    BfOut bfNone = {nullptr, nullptr, 1.0f};
    BfOut bfQ = {qh, ql, 0.125f};
    BfOut bfK = {kh, kl, 1.0f};
    BfOut bfV = {vh, vl, 1.0f};

    cudaFuncSetAttribute(fused_gemm,
                         cudaFuncAttributeMaxDynamicSharedMemorySize, GEMM_SMEM);
    cudaFuncSetAttribute(attn_hmma,
                         cudaFuncAttributeMaxDynamicSharedMemorySize, ATTN_SMEM);

    dim3 gemmGrid(BT_ / 128);
    dim3 attnGrid(8, B_ * H_);

    embed_rms_kernel<<<BT_ / 8, 256>>>(seq, item, pos, emb_s, x);

    for (int l = 0; l < L_; l++) {
        size_t wo = (size_t)l * D_ * D_;
        size_t bo = (size_t)l * D_;

        // QKVU: rms(x)*ln1 folded in; silu; U -> fp32, Q/K/V -> bf16 hi/lo
        fused_gemm<<<gemmGrid, 512, GEMM_SMEM>>>(
            x, nullptr, ln1 + bo, 1,
            Uw + wo, Ub + bo, u,
            Vw + wo, Vb + bo, nullptr,
            Qw + wo, Qb + bo, nullptr,
            Kw + wo, Kb + bo, nullptr,
            bfNone, bfV, bfQ, bfK,
            nullptr, 4, 1);

        attn_hmma<<<attnGrid, 512, ATTN_SMEM>>>(qh, kh, kl, vh, vl, av);

        fused_gemm<<<gemmGrid, 512, GEMM_SMEM>>>(
            av, u, hstu + bo, 1,
            f2w + wo, f2b + bo, x,
            nullptr, nullptr, nullptr,
            nullptr, nullptr, nullptr,
            nullptr, nullptr, nullptr,
            bfNone, bfNone, bfNone, bfNone,
            x, 1, 0);

        fused_gemm<<<gemmGrid, 512, GEMM_SMEM>>>(
            x, nullptr, ln2 + bo, 1,
            c1w + wo, c1b + bo, tb,
            nullptr, nullptr, nullptr,
            nullptr, nullptr, nullptr,
            nullptr, nullptr, nullptr,
            bfNone, bfNone, bfNone, bfNone,
            nullptr, 1, 2);

        fused_gemm<<<gemmGrid, 512, GEMM_SMEM>>>(
            tb, nullptr, nullptr, 0,
            c2w + wo, c2b + bo, x,
            nullptr, nullptr, nullptr,
            nullptr, nullptr, nullptr,
            nullptr, nullptr, nullptr,
            bfNone, bfNone, bfNone, bfNone,
            x, 1, 0);
    }

    rms_kernel<<<BT_ / 8, 256>>>(x, last_s, out);
}

// round 12
// speedup vs baseline: 1.6057x; 1.1444x over previous
#include <cuda_runtime.h>
#include <cuda_bf16.h>
#include <math.h>
#include <stdint.h>

// Problem constants
#define B_ 8
#define T_ 2048
#define D_ 128
#define L_ 4
#define H_ 2
#define HD_ 64
#define BT_ (B_ * T_)          // 16384 rows
#define EPS_ 1e-8f

#define GP 132                 // smem pitch (floats) for 128-wide gemm tiles
#define GEMM_SMEM ((2 * 128 * GP + 128) * 4)

// ---------------------------------------------------------------------------
// Scratch buffers (allocation-free: __device__ globals)
// ---------------------------------------------------------------------------
__device__ float g_x [BT_ * D_];
__device__ float g_u [BT_ * D_];
__device__ float g_v [BT_ * D_];   // vh (lo unused)
__device__ float g_q [BT_ * D_];   // qh (lo unused)
__device__ float g_k [BT_ * D_];   // kh | kl
__device__ float g_av[BT_ * D_];
__device__ float g_t [BT_ * D_];

// bf16 split-output descriptor for fused_gemm (lo == nullptr -> hi only)
struct BfOut {
    __nv_bfloat16* hi;
    __nv_bfloat16* lo;
    float scale;
};

// ===========================================================================
// Small helpers
// ===========================================================================
__device__ __forceinline__ uint32_t smem_u32(const void* p) {
    uint32_t a;
    asm("{ .reg .u64 t; cvta.to.shared.u64 t, %1; cvt.u32.u64 %0, t; }"
        : "=r"(a) : "l"(p));
    return a;
}

#define CP16(saddr, gptr) \
    asm volatile("cp.async.cg.shared.global [%0], [%1], 16;" \
                 :: "r"((uint32_t)(saddr)), "l"(gptr) : "memory")
#define CP_COMMIT() asm volatile("cp.async.commit_group;" ::: "memory")
#define CP_WAIT0()  asm volatile("cp.async.wait_group 0;" ::: "memory")

__device__ __forceinline__ float tanh_approx(float x) {
    float r;
    asm("tanh.approx.f32 %0, %1;" : "=f"(r) : "f"(x));
    return r;
}

// silu via single-MUFU tanh: x*sigmoid(x) = x*0.5*(1+tanh(x/2))
__device__ __forceinline__ float silu_fast(float a) {
    return a * 0.5f * (1.0f + tanh_approx(0.5f * a));
}

// bf16 hi/lo split of an fp32 value
__device__ __forceinline__ void split_bf16(float x, __nv_bfloat16& h, __nv_bfloat16& l) {
    h = __float2bfloat16(x);
    l = __float2bfloat16(x - __bfloat162float(h));
}

__device__ __forceinline__ uint32_t bf16x2_hi(float x, float y) {
    __nv_bfloat162 t = __floats2bfloat162_rn(x, y);  // .x = x in low half
    return *reinterpret_cast<uint32_t*>(&t);
}
__device__ __forceinline__ uint32_t bf16x2_lo(float x, float y) {
    float xh = __bfloat162float(__float2bfloat16(x));
    float yh = __bfloat162float(__float2bfloat16(y));
    __nv_bfloat162 t = __floats2bfloat162_rn(x - xh, y - yh);
    return *reinterpret_cast<uint32_t*>(&t);
}

// mma.sync m16n8k16 bf16 -> f32 (accumulate in place)
__device__ __forceinline__ void mma16816(float* c, const uint32_t* a,
                                         uint32_t b0, uint32_t b1) {
    asm volatile(
        "mma.sync.aligned.m16n8k16.row.col.f32.bf16.bf16.f32 "
        "{%0,%1,%2,%3}, {%4,%5,%6,%7}, {%8,%9}, {%0,%1,%2,%3};"
        : "+f"(c[0]), "+f"(c[1]), "+f"(c[2]), "+f"(c[3])
        : "r"(a[0]), "r"(a[1]), "r"(a[2]), "r"(a[3]), "r"(b0), "r"(b1));
}

// ldmatrix x2 transposed (for V B-fragments from row-major V[key][d])
__device__ __forceinline__ void ldsm_x2_trans(uint32_t& r0, uint32_t& r1, uint32_t addr) {
    asm volatile("ldmatrix.sync.aligned.m8n8.x2.trans.shared.b16 {%0,%1}, [%2];"
                 : "=r"(r0), "=r"(r1) : "r"(addr));
}

// ===========================================================================
// Elementwise RMS kernels
// ===========================================================================
__global__ void rms_kernel(const float* __restrict__ in,
                           const float* __restrict__ sc,
                           float* __restrict__ out) {
    int warp = threadIdx.x >> 5, lane = threadIdx.x & 31;
    size_t row = (size_t)blockIdx.x * 8 + warp;
    float4 v = *(const float4*)(in + row * 128 + lane * 4);
    float ss = v.x * v.x + v.y * v.y + v.z * v.z + v.w * v.w;
    #pragma unroll
    for (int o = 16; o > 0; o >>= 1) ss += __shfl_xor_sync(0xffffffffu, ss, o);
    float r = rsqrtf(ss * (1.0f / 128.0f) + EPS_);
    float4 s = *(const float4*)(sc + lane * 4);
    *(float4*)(out + row * 128 + lane * 4) =
        make_float4(v.x * r * s.x, v.y * r * s.y, v.z * r * s.z, v.w * r * s.w);
}

__global__ void embed_rms_kernel(const int* __restrict__ seq,
                                 const float* __restrict__ item,
                                 const float* __restrict__ pos,
                                 const float* __restrict__ sc,
                                 float* __restrict__ out) {
    int warp = threadIdx.x >> 5, lane = threadIdx.x & 31;
    size_t row = (size_t)blockIdx.x * 8 + warp;
    int t = (int)(row & (T_ - 1));
    int id = seq[row];
    float4 a = *(const float4*)(item + (size_t)id * 128 + lane * 4);
    float4 p = *(const float4*)(pos + (size_t)(t + 1) * 128 + lane * 4);
    float4 v = make_float4(a.x + p.x, a.y + p.y, a.z + p.z, a.w + p.w);
    float ss = v.x * v.x + v.y * v.y + v.z * v.z + v.w * v.w;
    #pragma unroll
    for (int o = 16; o > 0; o >>= 1) ss += __shfl_xor_sync(0xffffffffu, ss, o);
    float r = rsqrtf(ss * (1.0f / 128.0f) + EPS_);
    float4 s = *(const float4*)(sc + lane * 4);
    *(float4*)(out + row * 128 + lane * 4) =
        make_float4(v.x * r * s.x, v.y * r * s.y, v.z * r * s.z, v.w * r * s.w);
}

// ===========================================================================
// Fused GEMM (fp32 SIMT), 512 threads, 4x8 outputs/thread.
// Output: fp32, or bf16 (hi only or hi/lo split) when bf.hi != nullptr.
// ===========================================================================
__global__ void __launch_bounds__(512)
fused_gemm(const float* __restrict__ A,
           const float* __restrict__ mul,
           const float* __restrict__ scvec,
           int use_rms,
           const float* __restrict__ W0, const float* __restrict__ B0, float* __restrict__ O0,
           const float* __restrict__ W1, const float* __restrict__ B1, float* __restrict__ O1,
           const float* __restrict__ W2, const float* __restrict__ B2, float* __restrict__ O2,
           const float* __restrict__ W3, const float* __restrict__ B3, float* __restrict__ O3,
           BfOut bf0, BfOut bf1, BfOut bf2, BfOut bf3,
           const float* __restrict__ res,
           int nw, int act) {
    extern __shared__ float sm[];
    float* As = sm;
    float* Ws = As + 128 * GP;
    float* rr = Ws + 128 * GP;

    int tid = threadIdx.x;
    int row0 = blockIdx.x * 128;

    for (int idx = tid; idx < 128 * 32; idx += 512) {
        int r = idx >> 5, c4 = (idx & 31) << 2;
        *(float4*)(As + r * GP + c4) =
            *(const float4*)(A + (size_t)(row0 + r) * 128 + c4);
    }
    __syncthreads();

    if (use_rms) {
        int w = tid >> 5, lane = tid & 31;
        for (int r = w; r < 128; r += 16) {
            float4 v = *(const float4*)(As + r * GP + lane * 4);
            float ss = v.x * v.x + v.y * v.y + v.z * v.z + v.w * v.w;
            #pragma unroll
            for (int off = 16; off > 0; off >>= 1)
                ss += __shfl_xor_sync(0xffffffffu, ss, off);
            if (lane == 0) rr[r] = rsqrtf(ss * (1.0f / 128.0f) + EPS_);
        }
    } else {
        if (tid < 128) rr[tid] = 1.0f;
    }
    __syncthreads();

    if (mul) {
        for (int idx = tid; idx < 128 * 32; idx += 512) {
            int r = idx >> 5, c4 = (idx & 31) << 2;
            float4 m = *(const float4*)(mul + (size_t)(row0 + r) * 128 + c4);
            float4 a = *(float4*)(As + r * GP + c4);
            a.x *= m.x; a.y *= m.y; a.z *= m.z; a.w *= m.w;
            *(float4*)(As + r * GP + c4) = a;
        }
    }

    int ti = tid >> 4, tj = tid & 15;
    int r0 = ti * 4, c0 = tj * 8;

    const float* Wp[4] = {W0, W1, W2, W3};
    const float* Bp[4] = {B0, B1, B2, B3};
    float*       Op[4] = {O0, O1, O2, O3};
    BfOut        Bf[4] = {bf0, bf1, bf2, bf3};

    for (int wi = 0; wi < nw; wi++) {
        const float* W = Wp[wi];
        for (int idx = tid; idx < 128 * 32; idx += 512) {
            int r = idx >> 5, c4 = (idx & 31) << 2;
            float s = scvec ? scvec[r] : 1.0f;
            float4 v = *(const float4*)(W + (size_t)r * 128 + c4);
            v.x *= s; v.y *= s; v.z *= s; v.w *= s;
            *(float4*)(Ws + r * GP + c4) = v;
        }
        __syncthreads();

        float acc[4][8];
        #pragma unroll
        for (int i = 0; i < 4; i++)
            #pragma unroll
            for (int j = 0; j < 8; j++) acc[i][j] = 0.0f;

        for (int k = 0; k < 128; k += 4) {
            float4 w0[4], w1[4];
            #pragma unroll
            for (int kk = 0; kk < 4; kk++) {
                w0[kk] = *(const float4*)(Ws + (k + kk) * GP + c0);
                w1[kk] = *(const float4*)(Ws + (k + kk) * GP + c0 + 4);
            }
            #pragma unroll
            for (int i = 0; i < 4; i++) {
                float4 a = *(const float4*)(As + (r0 + i) * GP + k);
                acc[i][0] += a.x * w0[0].x + a.y * w0[1].x + a.z * w0[2].x + a.w * w0[3].x;
                acc[i][1] += a.x * w0[0].y + a.y * w0[1].y + a.z * w0[2].y + a.w * w0[3].y;
                acc[i][2] += a.x * w0[0].z + a.y * w0[1].z + a.z * w0[2].z + a.w * w0[3].z;
                acc[i][3] += a.x * w0[0].w + a.y * w0[1].w + a.z * w0[2].w + a.w * w0[3].w;
                acc[i][4] += a.x * w1[0].x + a.y * w1[1].x + a.z * w1[2].x + a.w * w1[3].x;
                acc[i][5] += a.x * w1[0].y + a.y * w1[1].y + a.z * w1[2].y + a.w * w1[3].y;
                acc[i][6] += a.x * w1[0].z + a.y * w1[1].z + a.z * w1[2].z + a.w * w1[3].z;
                acc[i][7] += a.x * w1[0].w + a.y * w1[1].w + a.z * w1[2].w + a.w * w1[3].w;
            }
        }

        const float* Bv = Bp[wi];
        float* Ov = Op[wi];
        BfOut bfo = Bf[wi];
        #pragma unroll
        for (int i = 0; i < 4; i++) {
            float rri = rr[r0 + i];
            size_t grow = (size_t)(row0 + r0 + i) * 128;
            float vout[8];
            #pragma unroll
            for (int j = 0; j < 8; j++) {
                float v = acc[i][j] * rri + Bv[c0 + j];
                if (act == 1) {
                    v = v * __fdividef(1.0f, 1.0f + __expf(-v));
                } else if (act == 2) {
                    v = 0.5f * v * (1.0f + erff(v * 0.70710678118654752f));
                }
                vout[j] = v;
            }
            if (bfo.hi) {
                if (bfo.lo) {
                    __nv_bfloat16 hh[8], ll[8];
                    #pragma unroll
                    for (int j = 0; j < 8; j++)
                        split_bf16(vout[j] * bfo.scale, hh[j], ll[j]);
                    *(uint4*)(bfo.hi + grow + c0) = *(const uint4*)hh;
                    *(uint4*)(bfo.lo + grow + c0) = *(const uint4*)ll;
                } else {
                    __nv_bfloat16 hh[8];
                    #pragma unroll
                    for (int j = 0; j < 8; j++)
                        hh[j] = __float2bfloat16(vout[j] * bfo.scale);
                    *(uint4*)(bfo.hi + grow + c0) = *(const uint4*)hh;
                }
            } else {
                if (res) {
                    #pragma unroll
                    for (int j = 0; j < 8; j++) vout[j] += res[grow + c0 + j];
                }
                *(float4*)(Ov + grow + c0)     = make_float4(vout[0], vout[1], vout[2], vout[3]);
                *(float4*)(Ov + grow + c0 + 4) = make_float4(vout[4], vout[5], vout[6], vout[7]);
            }
        }
        __syncthreads();
    }
}

// ===========================================================================
// HMMA HSTU attention, double-buffered cp.async pipeline.
// QK: 2-pass (Qh·Kh + Qh·Kl). PV: 2-pass (Phi·Vh + Plo·Vh); V hi-only.
// Gate uses single-MUFU tanh.approx silu. grid = (8, 16), block = 512.
// Warp pair (2p, 2p+1) owns Q-rows [16p,16p+16); warps split S-cols (sh).
// Block handles q-tiles qp and 15-qp (causal load balancing).
// ===========================================================================
#define QKP 72                 // row pitch in bf16 elements (144B -> conflict-free)
#define TILEB 18432            // one 128 x QKP bf16 tile
#define SM_QH  0
#define SM_K0H (1 * TILEB)     // buf0 K hi (reused as combine scratch at end)
#define SM_K0L (2 * TILEB)
#define SM_V0H (3 * TILEB)
#define SM_K1H (4 * TILEB)
#define SM_K1L (5 * TILEB)
#define SM_V1H (6 * TILEB)
#define ATTN_SMEM (7 * TILEB)   // 129024 bytes

__global__ void __launch_bounds__(512, 1)
attn_hmma(const __nv_bfloat16* __restrict__ Qh,
          const __nv_bfloat16* __restrict__ Kh, const __nv_bfloat16* __restrict__ Kl,
          const __nv_bfloat16* __restrict__ Vh,
          float* __restrict__ O) {
    extern __shared__ char smc[];
    uint32_t sb = smem_u32(smc);

    int tid  = threadIdx.x;
    int warp = tid >> 5;       // 0..15
    int lane = tid & 31;
    int pair = warp >> 1;      // 0..7
    int sh   = warp & 1;       // column half
    int g    = lane >> 2;      // fragment group row 0..7
    int c2   = lane & 3;       // fragment group col 0..3
    int m0   = pair * 16;      // pair's S/O row base (0..112)

    int bh = blockIdx.y;
    int b = bh >> 1, h = bh & 1;
    int coloff = h * HD_;
    int qp = blockIdx.x;

    const uint32_t KHo[2] = {sb + SM_K0H, sb + SM_K1H};
    const uint32_t KLo[2] = {sb + SM_K0L, sb + SM_K1L};
    const uint32_t VHo[2] = {sb + SM_V0H, sb + SM_V1H};

    for (int half = 0; half < 2; half++) {
        int qt = half ? (15 - qp) : qp;
        int qbase = b * T_ + qt * 128;

        __syncthreads();   // previous q-tile consumers / scratch users done

        // ---- async copy: Q tile (hi only) + K/V tile 0 ----
        for (int idx = tid; idx < 128 * 8; idx += 512) {
            int r = idx >> 3, c8 = (idx & 7) << 3;
            size_t goff = (size_t)(qbase + r) * 128 + coloff + c8;
            uint32_t soff = (uint32_t)(r * QKP + c8) * 2;
            CP16(sb + SM_QH + soff, Qh + goff);
        }
        {
            int kbase0 = b * T_;   // kt = 0
            for (int idx = tid; idx < 128 * 8; idx += 512) {
                int r = idx >> 3, c8 = (idx & 7) << 3;
                size_t goff = (size_t)(kbase0 + r) * 128 + coloff + c8;
                uint32_t soff = (uint32_t)(r * QKP + c8) * 2;
                CP16(KHo[0] + soff, Kh + goff);
                CP16(KLo[0] + soff, Kl + goff);
                CP16(VHo[0] + soff, Vh + goff);
            }
        }
        CP_COMMIT();
        CP_WAIT0();
        __syncthreads();

        // ---- A fragments (hi only) for this pair's 16 Q rows ----
        uint32_t Ah[4][4];
        #pragma unroll
        for (int ks = 0; ks < 4; ks++) {
            uint32_t o00 = (uint32_t)((m0 + g)     * QKP + 16 * ks + 2 * c2) * 2;
            uint32_t o01 = (uint32_t)((m0 + g + 8) * QKP + 16 * ks + 2 * c2) * 2;
            Ah[ks][0] = *(const uint32_t*)(smc + SM_QH + o00);
            Ah[ks][1] = *(const uint32_t*)(smc + SM_QH + o01);
            Ah[ks][2] = *(const uint32_t*)(smc + SM_QH + o00 + 16);
            Ah[ks][3] = *(const uint32_t*)(smc + SM_QH + o01 + 16);
        }

        float Of[8][4];
        #pragma unroll
        for (int nf = 0; nf < 8; nf++)
            #pragma unroll
            for (int r = 0; r < 4; r++) Of[nf][r] = 0.0f;
        float ds0 = 0.0f, ds1 = 0.0f;

        int row0 = qt * 128 + m0 + g;       // global (in-seq) rows of this lane
        int row1 = row0 + 8;

        for (int kt = 0; kt <= qt; kt++) {
            int p = kt & 1;

            // ---- prefetch tile kt+1 into the other buffer ----
            if (kt < qt) {
                int kb1 = b * T_ + (kt + 1) * 128;
                int q1 = (kt + 1) & 1;
                for (int idx = tid; idx < 128 * 8; idx += 512) {
                    int r = idx >> 3, c8 = (idx & 7) << 3;
                    size_t goff = (size_t)(kb1 + r) * 128 + coloff + c8;
                    uint32_t soff = (uint32_t)(r * QKP + c8) * 2;
                    CP16(KHo[q1] + soff, Kh + goff);
                    CP16(KLo[q1] + soff, Kl + goff);
                    CP16(VHo[q1] + soff, Vh + goff);
                }
                CP_COMMIT();
            }

            const char* kh_s = (const char*)smc + (KHo[p] - sb);
            const char* kl_s = (const char*)smc + (KLo[p] - sb);
            uint32_t vh_b = VHo[p];

            // ---- this warp's S-column half ----
            uint32_t Phi[4][4], Plo[4][4];

            // S = Q @ K^T (2-pass: Qh·Kh + Qh·Kl), gate, pack P frags
            #pragma unroll
            for (int jj = 0; jj < 4; jj++) {
                int jpv = 4 * sh + jj;      // PV k-step index (0..7)
                #pragma unroll
                for (int e = 0; e < 2; e++) {
                    int nfr = 2 * jpv + e;  // S n-fragment (0..15)
                    float cf[4] = {0.0f, 0.0f, 0.0f, 0.0f};
                    uint32_t kb = (uint32_t)((8 * nfr + g) * QKP + 2 * c2) * 2;
                    #pragma unroll
                    for (int ks = 0; ks < 4; ks++) {
                        uint32_t o = kb + 32 * ks;
                        uint32_t bh0 = *(const uint32_t*)(kh_s + o);
                        uint32_t bh1 = *(const uint32_t*)(kh_s + o + 16);
                        uint32_t bl0 = *(const uint32_t*)(kl_s + o);
                        uint32_t bl1 = *(const uint32_t*)(kl_s + o + 16);
                        mma16816(cf, Ah[ks], bh0, bh1);
                        mma16816(cf, Ah[ks], bl0, bl1);
                    }
                    // gate: max(silu(a),0) via tanh.approx, causal mask
                    int colb = kt * 128 + 8 * nfr + 2 * c2;
                    float g0 = 0.0f, g1 = 0.0f, g2 = 0.0f, g3 = 0.0f;
                    if (cf[0] > 0.0f && colb     <= row0) g0 = silu_fast(cf[0]);
                    if (cf[1] > 0.0f && colb + 1 <= row0) g1 = silu_fast(cf[1]);
                    if (cf[2] > 0.0f && colb     <= row1) g2 = silu_fast(cf[2]);
                    if (cf[3] > 0.0f && colb + 1 <= row1) g3 = silu_fast(cf[3]);
                    ds0 += g0 + g1;
                    ds1 += g2 + g3;
                    Phi[jj][2 * e]     = bf16x2_hi(g0, g1);
                    Phi[jj][2 * e + 1] = bf16x2_hi(g2, g3);
                    Plo[jj][2 * e]     = bf16x2_lo(g0, g1);
                    Plo[jj][2 * e + 1] = bf16x2_lo(g2, g3);
                }
            }

            // O += P @ V for this warp's k-half (2-pass: Phi·Vh + Plo·Vh)
            #pragma unroll
            for (int jj = 0; jj < 4; jj++) {
                int k0v = 16 * (4 * sh + jj);
                uint32_t rowa = (uint32_t)((k0v + (lane & 15)) * QKP) * 2;
                #pragma unroll
                for (int nf = 0; nf < 8; nf++) {
                    uint32_t vh0, vh1;
                    ldsm_x2_trans(vh0, vh1, vh_b + rowa + (uint32_t)(16 * nf));
                    mma16816(Of[nf], Phi[jj], vh0, vh1);
                    mma16816(Of[nf], Plo[jj], vh0, vh1);
                }
            }

            CP_WAIT0();        // prefetched tile resident
            __syncthreads();   // all warps done reading buffer p
        }

        // ---- quad-reduce denominators within each warp ----
        ds0 += __shfl_xor_sync(0xffffffffu, ds0, 1);
        ds0 += __shfl_xor_sync(0xffffffffu, ds0, 2);
        ds1 += __shfl_xor_sync(0xffffffffu, ds1, 1);
        ds1 += __shfl_xor_sync(0xffffffffu, ds1, 2);

        // ---- combine the two column-half partials (scratch in K0 region) ----
        float* scr = (float*)(smc + SM_K0H + pair * 4352);
        if (sh == 1) {
            float* dst = scr + lane * 32;
            #pragma unroll
            for (int nf = 0; nf < 8; nf++) {
                dst[4 * nf + 0] = Of[nf][0];
                dst[4 * nf + 1] = Of[nf][1];
                dst[4 * nf + 2] = Of[nf][2];
                dst[4 * nf + 3] = Of[nf][3];
            }
            scr[1024 + lane * 2]     = ds0;
            scr[1024 + lane * 2 + 1] = ds1;
        }
        __syncthreads();

        if (sh == 0) {
            const float* src = scr + lane * 32;
            float dt0 = ds0 + scr[1024 + lane * 2];
            float dt1 = ds1 + scr[1024 + lane * 2 + 1];
            float f0 = (dt0 > 1e-12f) ? __fdividef(1.0f, dt0 + EPS_) : 0.0f;
            float f1 = (dt1 > 1e-12f) ? __fdividef(1.0f, dt1 + EPS_) : 0.0f;

            size_t orow0 = (size_t)(qbase + m0 + g) * 128 + coloff;
            size_t orow1 = orow0 + 8 * 128;
            #pragma unroll
            for (int nf = 0; nf < 8; nf++) {
                int c = 8 * nf + 2 * c2;
                float o0 = Of[nf][0] + src[4 * nf + 0];
                float o1 = Of[nf][1] + src[4 * nf + 1];
                float o2 = Of[nf][2] + src[4 * nf + 2];
                float o3 = Of[nf][3] + src[4 * nf + 3];
                *(float2*)(O + orow0 + c) = make_float2(o0 * f0, o1 * f0);
                *(float2*)(O + orow1 + c) = make_float2(o2 * f1, o3 * f1);
            }
        }
    }
}

// ===========================================================================
// Host orchestration
// ===========================================================================
extern "C" void kernel_launch(void* const* d_in, const int* in_sizes, int n_in,
                              void* d_out, int out_size) {
    const int*   seq    = (const int*)  d_in[0];
    // d_in[1] = attn_mask (causal tril) — synthesized in-kernel
    const float* item   = (const float*)d_in[2];
    const float* pos    = (const float*)d_in[3];
    const float* emb_s  = (const float*)d_in[4];
    const float* ln1    = (const float*)d_in[5];
    const float* Uw     = (const float*)d_in[6];
    const float* Ub     = (const float*)d_in[7];
    const float* Vw     = (const float*)d_in[8];
    const float* Vb     = (const float*)d_in[9];
    const float* Qw     = (const float*)d_in[10];
    const float* Qb     = (const float*)d_in[11];
    const float* Kw     = (const float*)d_in[12];
    const float* Kb     = (const float*)d_in[13];
    const float* f2w    = (const float*)d_in[14];
    const float* f2b    = (const float*)d_in[15];
    const float* hstu   = (const float*)d_in[16];
    const float* ln2    = (const float*)d_in[17];
    const float* c1w    = (const float*)d_in[18];
    const float* c1b    = (const float*)d_in[19];
    const float* c2w    = (const float*)d_in[20];
    const float* c2b    = (const float*)d_in[21];
    const float* last_s = (const float*)d_in[22];
    float* out = (float*)d_out;

    float *x, *u, *v, *q, *k, *av, *tb;
    cudaGetSymbolAddress((void**)&x,  g_x);
    cudaGetSymbolAddress((void**)&u,  g_u);
    cudaGetSymbolAddress((void**)&v,  g_v);
    cudaGetSymbolAddress((void**)&q,  g_q);
    cudaGetSymbolAddress((void**)&k,  g_k);
    cudaGetSymbolAddress((void**)&av, g_av);
    cudaGetSymbolAddress((void**)&tb, g_t);

    __nv_bfloat16* qh = (__nv_bfloat16*)q;
    __nv_bfloat16* kh = (__nv_bfloat16*)k;
    __nv_bfloat16* kl = kh + (size_t)BT_ * 128;
    __nv_bfloat16* vh = (__nv_bfloat16*)v;

    BfOut bfNone = {nullptr, nullptr, 1.0f};
    BfOut bfQ = {qh, nullptr, 0.125f};
    BfOut bfK = {kh, kl, 1.0f};
    BfOut bfV = {vh, nullptr, 1.0f};

    cudaFuncSetAttribute(fused_gemm,
                         cudaFuncAttributeMaxDynamicSharedMemorySize, GEMM_SMEM);
    cudaFuncSetAttribute(attn_hmma,
                         cudaFuncAttributeMaxDynamicSharedMemorySize, ATTN_SMEM);

    dim3 gemmGrid(BT_ / 128);
    dim3 attnGrid(8, B_ * H_);

    embed_rms_kernel<<<BT_ / 8, 256>>>(seq, item, pos, emb_s, x);

    for (int l = 0; l < L_; l++) {
        size_t wo = (size_t)l * D_ * D_;
        size_t bo = (size_t)l * D_;

        // QKVU: rms(x)*ln1 folded in; silu; U -> fp32, Q/V -> bf16 hi,
        // K -> bf16 hi/lo
        fused_gemm<<<gemmGrid, 512, GEMM_SMEM>>>(
            x, nullptr, ln1 + bo, 1,
            Uw + wo, Ub + bo, u,
            Vw + wo, Vb + bo, nullptr,
            Qw + wo, Qb + bo, nullptr,
            Kw + wo, Kb + bo, nullptr,
            bfNone, bfV, bfQ, bfK,
            nullptr, 4, 1);

        attn_hmma<<<attnGrid, 512, ATTN_SMEM>>>(qh, kh, kl, vh, av);

        fused_gemm<<<gemmGrid, 512, GEMM_SMEM>>>(
            av, u, hstu + bo, 1,
            f2w + wo, f2b + bo, x,
            nullptr, nullptr, nullptr,
            nullptr, nullptr, nullptr,
            nullptr, nullptr, nullptr,
            bfNone, bfNone, bfNone, bfNone,
            x, 1, 0);

        fused_gemm<<<gemmGrid, 512, GEMM_SMEM>>>(
            x, nullptr, ln2 + bo, 1,
            c1w + wo, c1b + bo, tb,
            nullptr, nullptr, nullptr,
            nullptr, nullptr, nullptr,
            nullptr, nullptr, nullptr,
            bfNone, bfNone, bfNone, bfNone,
            nullptr, 1, 2);

        fused_gemm<<<gemmGrid, 512, GEMM_SMEM>>>(
            tb, nullptr, nullptr, 0,
            c2w + wo, c2b + bo, x,
            nullptr, nullptr, nullptr,
            nullptr, nullptr, nullptr,
            nullptr, nullptr, nullptr,
            bfNone, bfNone, bfNone, bfNone,
            x, 1, 0);
    }

    rms_kernel<<<BT_ / 8, 256>>>(x, last_s, out);
}

// round 13
// speedup vs baseline: 1.6886x; 1.0517x over previous
#include <cuda_runtime.h>
#include <cuda_bf16.h>
#include <math.h>
#include <stdint.h>

// Problem constants
#define B_ 8
#define T_ 2048
#define D_ 128
#define L_ 4
#define H_ 2
#define HD_ 64
#define BT_ (B_ * T_)          // 16384 rows
#define EPS_ 1e-8f

#define GP 132                 // smem pitch (floats) for 128-wide gemm tiles
#define GEMM_SMEM ((2 * 128 * GP + 128) * 4)

// ---------------------------------------------------------------------------
// Scratch buffers (allocation-free: __device__ globals)
// ---------------------------------------------------------------------------
__device__ float g_x [BT_ * D_];
__device__ float g_u [BT_ * D_];
__device__ float g_v [BT_ * D_];   // vh (lo unused)
__device__ float g_q [BT_ * D_];   // qh (lo unused)
__device__ float g_k [BT_ * D_];   // kh | kl
__device__ float g_av[BT_ * D_];
__device__ float g_t [BT_ * D_];

// bf16 split-output descriptor for fused_gemm (lo == nullptr -> hi only)
struct BfOut {
    __nv_bfloat16* hi;
    __nv_bfloat16* lo;
    float scale;
};

// ===========================================================================
// Small helpers
// ===========================================================================
__device__ __forceinline__ uint32_t smem_u32(const void* p) {
    uint32_t a;
    asm("{ .reg .u64 t; cvta.to.shared.u64 t, %1; cvt.u32.u64 %0, t; }"
        : "=r"(a) : "l"(p));
    return a;
}

#define CP16(saddr, gptr) \
    asm volatile("cp.async.cg.shared.global [%0], [%1], 16;" \
                 :: "r"((uint32_t)(saddr)), "l"(gptr) : "memory")
#define CP_COMMIT() asm volatile("cp.async.commit_group;" ::: "memory")
#define CP_WAIT0()  asm volatile("cp.async.wait_group 0;" ::: "memory")

__device__ __forceinline__ float tanh_approx(float x) {
    float r;
    asm("tanh.approx.f32 %0, %1;" : "=f"(r) : "f"(x));
    return r;
}

// silu via single-MUFU tanh: x*sigmoid(x) = x*0.5*(1+tanh(x/2))
__device__ __forceinline__ float silu_fast(float a) {
    return a * 0.5f * (1.0f + tanh_approx(0.5f * a));
}

// bf16 hi/lo split of an fp32 value
__device__ __forceinline__ void split_bf16(float x, __nv_bfloat16& h, __nv_bfloat16& l) {
    h = __float2bfloat16(x);
    l = __float2bfloat16(x - __bfloat162float(h));
}

__device__ __forceinline__ uint32_t bf16x2_hi(float x, float y) {
    __nv_bfloat162 t = __floats2bfloat162_rn(x, y);  // .x = x in low half
    return *reinterpret_cast<uint32_t*>(&t);
}

// mma.sync m16n8k16 bf16 -> f32 (accumulate in place)
__device__ __forceinline__ void mma16816(float* c, const uint32_t* a,
                                         uint32_t b0, uint32_t b1) {
    asm volatile(
        "mma.sync.aligned.m16n8k16.row.col.f32.bf16.bf16.f32 "
        "{%0,%1,%2,%3}, {%4,%5,%6,%7}, {%8,%9}, {%0,%1,%2,%3};"
        : "+f"(c[0]), "+f"(c[1]), "+f"(c[2]), "+f"(c[3])
        : "r"(a[0]), "r"(a[1]), "r"(a[2]), "r"(a[3]), "r"(b0), "r"(b1));
}

// ldmatrix x2 transposed (for V B-fragments from row-major V[key][d])
__device__ __forceinline__ void ldsm_x2_trans(uint32_t& r0, uint32_t& r1, uint32_t addr) {
    asm volatile("ldmatrix.sync.aligned.m8n8.x2.trans.shared.b16 {%0,%1}, [%2];"
                 : "=r"(r0), "=r"(r1) : "r"(addr));
}

// ===========================================================================
// Elementwise RMS kernels
// ===========================================================================
__global__ void rms_kernel(const float* __restrict__ in,
                           const float* __restrict__ sc,
                           float* __restrict__ out) {
    int warp = threadIdx.x >> 5, lane = threadIdx.x & 31;
    size_t row = (size_t)blockIdx.x * 8 + warp;
    float4 v = *(const float4*)(in + row * 128 + lane * 4);
    float ss = v.x * v.x + v.y * v.y + v.z * v.z + v.w * v.w;
    #pragma unroll
    for (int o = 16; o > 0; o >>= 1) ss += __shfl_xor_sync(0xffffffffu, ss, o);
    float r = rsqrtf(ss * (1.0f / 128.0f) + EPS_);
    float4 s = *(const float4*)(sc + lane * 4);
    *(float4*)(out + row * 128 + lane * 4) =
        make_float4(v.x * r * s.x, v.y * r * s.y, v.z * r * s.z, v.w * r * s.w);
}

__global__ void embed_rms_kernel(const int* __restrict__ seq,
                                 const float* __restrict__ item,
                                 const float* __restrict__ pos,
                                 const float* __restrict__ sc,
                                 float* __restrict__ out) {
    int warp = threadIdx.x >> 5, lane = threadIdx.x & 31;
    size_t row = (size_t)blockIdx.x * 8 + warp;
    int t = (int)(row & (T_ - 1));
    int id = seq[row];
    float4 a = *(const float4*)(item + (size_t)id * 128 + lane * 4);
    float4 p = *(const float4*)(pos + (size_t)(t + 1) * 128 + lane * 4);
    float4 v = make_float4(a.x + p.x, a.y + p.y, a.z + p.z, a.w + p.w);
    float ss = v.x * v.x + v.y * v.y + v.z * v.z + v.w * v.w;
    #pragma unroll
    for (int o = 16; o > 0; o >>= 1) ss += __shfl_xor_sync(0xffffffffu, ss, o);
    float r = rsqrtf(ss * (1.0f / 128.0f) + EPS_);
    float4 s = *(const float4*)(sc + lane * 4);
    *(float4*)(out + row * 128 + lane * 4) =
        make_float4(v.x * r * s.x, v.y * r * s.y, v.z * r * s.z, v.w * r * s.w);
}

// ===========================================================================
// Fused GEMM (fp32 SIMT), 512 threads, 4x8 outputs/thread.
// Output: fp32, or bf16 (hi only or hi/lo split) when bf.hi != nullptr.
// ===========================================================================
__global__ void __launch_bounds__(512)
fused_gemm(const float* __restrict__ A,
           const float* __restrict__ mul,
           const float* __restrict__ scvec,
           int use_rms,
           const float* __restrict__ W0, const float* __restrict__ B0, float* __restrict__ O0,
           const float* __restrict__ W1, const float* __restrict__ B1, float* __restrict__ O1,
           const float* __restrict__ W2, const float* __restrict__ B2, float* __restrict__ O2,
           const float* __restrict__ W3, const float* __restrict__ B3, float* __restrict__ O3,
           BfOut bf0, BfOut bf1, BfOut bf2, BfOut bf3,
           const float* __restrict__ res,
           int nw, int act) {
    extern __shared__ float sm[];
    float* As = sm;
    float* Ws = As + 128 * GP;
    float* rr = Ws + 128 * GP;

    int tid = threadIdx.x;
    int row0 = blockIdx.x * 128;

    for (int idx = tid; idx < 128 * 32; idx += 512) {
        int r = idx >> 5, c4 = (idx & 31) << 2;
        *(float4*)(As + r * GP + c4) =
            *(const float4*)(A + (size_t)(row0 + r) * 128 + c4);
    }
    __syncthreads();

    if (use_rms) {
        int w = tid >> 5, lane = tid & 31;
        for (int r = w; r < 128; r += 16) {
            float4 v = *(const float4*)(As + r * GP + lane * 4);
            float ss = v.x * v.x + v.y * v.y + v.z * v.z + v.w * v.w;
            #pragma unroll
            for (int off = 16; off > 0; off >>= 1)
                ss += __shfl_xor_sync(0xffffffffu, ss, off);
            if (lane == 0) rr[r] = rsqrtf(ss * (1.0f / 128.0f) + EPS_);
        }
    } else {
        if (tid < 128) rr[tid] = 1.0f;
    }
    __syncthreads();

    if (mul) {
        for (int idx = tid; idx < 128 * 32; idx += 512) {
            int r = idx >> 5, c4 = (idx & 31) << 2;
            float4 m = *(const float4*)(mul + (size_t)(row0 + r) * 128 + c4);
            float4 a = *(float4*)(As + r * GP + c4);
            a.x *= m.x; a.y *= m.y; a.z *= m.z; a.w *= m.w;
            *(float4*)(As + r * GP + c4) = a;
        }
    }

    int ti = tid >> 4, tj = tid & 15;
    int r0 = ti * 4, c0 = tj * 8;

    const float* Wp[4] = {W0, W1, W2, W3};
    const float* Bp[4] = {B0, B1, B2, B3};
    float*       Op[4] = {O0, O1, O2, O3};
    BfOut        Bf[4] = {bf0, bf1, bf2, bf3};

    for (int wi = 0; wi < nw; wi++) {
        const float* W = Wp[wi];
        for (int idx = tid; idx < 128 * 32; idx += 512) {
            int r = idx >> 5, c4 = (idx & 31) << 2;
            float s = scvec ? scvec[r] : 1.0f;
            float4 v = *(const float4*)(W + (size_t)r * 128 + c4);
            v.x *= s; v.y *= s; v.z *= s; v.w *= s;
            *(float4*)(Ws + r * GP + c4) = v;
        }
        __syncthreads();

        float acc[4][8];
        #pragma unroll
        for (int i = 0; i < 4; i++)
            #pragma unroll
            for (int j = 0; j < 8; j++) acc[i][j] = 0.0f;

        for (int k = 0; k < 128; k += 4) {
            float4 w0[4], w1[4];
            #pragma unroll
            for (int kk = 0; kk < 4; kk++) {
                w0[kk] = *(const float4*)(Ws + (k + kk) * GP + c0);
                w1[kk] = *(const float4*)(Ws + (k + kk) * GP + c0 + 4);
            }
            #pragma unroll
            for (int i = 0; i < 4; i++) {
                float4 a = *(const float4*)(As + (r0 + i) * GP + k);
                acc[i][0] += a.x * w0[0].x + a.y * w0[1].x + a.z * w0[2].x + a.w * w0[3].x;
                acc[i][1] += a.x * w0[0].y + a.y * w0[1].y + a.z * w0[2].y + a.w * w0[3].y;
                acc[i][2] += a.x * w0[0].z + a.y * w0[1].z + a.z * w0[2].z + a.w * w0[3].z;
                acc[i][3] += a.x * w0[0].w + a.y * w0[1].w + a.z * w0[2].w + a.w * w0[3].w;
                acc[i][4] += a.x * w1[0].x + a.y * w1[1].x + a.z * w1[2].x + a.w * w1[3].x;
                acc[i][5] += a.x * w1[0].y + a.y * w1[1].y + a.z * w1[2].y + a.w * w1[3].y;
                acc[i][6] += a.x * w1[0].z + a.y * w1[1].z + a.z * w1[2].z + a.w * w1[3].z;
                acc[i][7] += a.x * w1[0].w + a.y * w1[1].w + a.z * w1[2].w + a.w * w1[3].w;
            }
        }

        const float* Bv = Bp[wi];
        float* Ov = Op[wi];
        BfOut bfo = Bf[wi];
        #pragma unroll
        for (int i = 0; i < 4; i++) {
            float rri = rr[r0 + i];
            size_t grow = (size_t)(row0 + r0 + i) * 128;
            float vout[8];
            #pragma unroll
            for (int j = 0; j < 8; j++) {
                float v = acc[i][j] * rri + Bv[c0 + j];
                if (act == 1) {
                    v = v * __fdividef(1.0f, 1.0f + __expf(-v));
                } else if (act == 2) {
                    v = 0.5f * v * (1.0f + erff(v * 0.70710678118654752f));
                }
                vout[j] = v;
            }
            if (bfo.hi) {
                if (bfo.lo) {
                    __nv_bfloat16 hh[8], ll[8];
                    #pragma unroll
                    for (int j = 0; j < 8; j++)
                        split_bf16(vout[j] * bfo.scale, hh[j], ll[j]);
                    *(uint4*)(bfo.hi + grow + c0) = *(const uint4*)hh;
                    *(uint4*)(bfo.lo + grow + c0) = *(const uint4*)ll;
                } else {
                    __nv_bfloat16 hh[8];
                    #pragma unroll
                    for (int j = 0; j < 8; j++)
                        hh[j] = __float2bfloat16(vout[j] * bfo.scale);
                    *(uint4*)(bfo.hi + grow + c0) = *(const uint4*)hh;
                }
            } else {
                if (res) {
                    #pragma unroll
                    for (int j = 0; j < 8; j++) vout[j] += res[grow + c0 + j];
                }
                *(float4*)(Ov + grow + c0)     = make_float4(vout[0], vout[1], vout[2], vout[3]);
                *(float4*)(Ov + grow + c0 + 4) = make_float4(vout[4], vout[5], vout[6], vout[7]);
            }
        }
        __syncthreads();
    }
}

// ===========================================================================
// HMMA HSTU attention, double-buffered cp.async pipeline.
// QK: 2-pass (Qh·Kh + Qh·Kl). PV: 1-pass (Phi·Vh); P and V bf16 hi only
// (quantization error averages out over the normalized attention sum).
// Gate uses single-MUFU tanh.approx silu. grid = (8, 16), block = 512.
// Warp pair (2p, 2p+1) owns Q-rows [16p,16p+16); warps split S-cols (sh).
// Block handles q-tiles qp and 15-qp (causal load balancing).
// ===========================================================================
#define QKP 72                 // row pitch in bf16 elements (144B -> conflict-free)
#define TILEB 18432            // one 128 x QKP bf16 tile
#define SM_QH  0
#define SM_K0H (1 * TILEB)     // buf0 K hi (reused as combine scratch at end)
#define SM_K0L (2 * TILEB)
#define SM_V0H (3 * TILEB)
#define SM_K1H (4 * TILEB)
#define SM_K1L (5 * TILEB)
#define SM_V1H (6 * TILEB)
#define ATTN_SMEM (7 * TILEB)   // 129024 bytes

__global__ void __launch_bounds__(512, 1)
attn_hmma(const __nv_bfloat16* __restrict__ Qh,
          const __nv_bfloat16* __restrict__ Kh, const __nv_bfloat16* __restrict__ Kl,
          const __nv_bfloat16* __restrict__ Vh,
          float* __restrict__ O) {
    extern __shared__ char smc[];
    uint32_t sb = smem_u32(smc);

    int tid  = threadIdx.x;
    int warp = tid >> 5;       // 0..15
    int lane = tid & 31;
    int pair = warp >> 1;      // 0..7
    int sh   = warp & 1;       // column half
    int g    = lane >> 2;      // fragment group row 0..7
    int c2   = lane & 3;       // fragment group col 0..3
    int m0   = pair * 16;      // pair's S/O row base (0..112)

    int bh = blockIdx.y;
    int b = bh >> 1, h = bh & 1;
    int coloff = h * HD_;
    int qp = blockIdx.x;

    const uint32_t KHo[2] = {sb + SM_K0H, sb + SM_K1H};
    const uint32_t KLo[2] = {sb + SM_K0L, sb + SM_K1L};
    const uint32_t VHo[2] = {sb + SM_V0H, sb + SM_V1H};

    for (int half = 0; half < 2; half++) {
        int qt = half ? (15 - qp) : qp;
        int qbase = b * T_ + qt * 128;

        __syncthreads();   // previous q-tile consumers / scratch users done

        // ---- async copy: Q tile (hi only) + K/V tile 0 ----
        for (int idx = tid; idx < 128 * 8; idx += 512) {
            int r = idx >> 3, c8 = (idx & 7) << 3;
            size_t goff = (size_t)(qbase + r) * 128 + coloff + c8;
            uint32_t soff = (uint32_t)(r * QKP + c8) * 2;
            CP16(sb + SM_QH + soff, Qh + goff);
        }
        {
            int kbase0 = b * T_;   // kt = 0
            for (int idx = tid; idx < 128 * 8; idx += 512) {
                int r = idx >> 3, c8 = (idx & 7) << 3;
                size_t goff = (size_t)(kbase0 + r) * 128 + coloff + c8;
                uint32_t soff = (uint32_t)(r * QKP + c8) * 2;
                CP16(KHo[0] + soff, Kh + goff);
                CP16(KLo[0] + soff, Kl + goff);
                CP16(VHo[0] + soff, Vh + goff);
            }
        }
        CP_COMMIT();
        CP_WAIT0();
        __syncthreads();

        // ---- A fragments (hi only) for this pair's 16 Q rows ----
        uint32_t Ah[4][4];
        #pragma unroll
        for (int ks = 0; ks < 4; ks++) {
            uint32_t o00 = (uint32_t)((m0 + g)     * QKP + 16 * ks + 2 * c2) * 2;
            uint32_t o01 = (uint32_t)((m0 + g + 8) * QKP + 16 * ks + 2 * c2) * 2;
            Ah[ks][0] = *(const uint32_t*)(smc + SM_QH + o00);
            Ah[ks][1] = *(const uint32_t*)(smc + SM_QH + o01);
            Ah[ks][2] = *(const uint32_t*)(smc + SM_QH + o00 + 16);
            Ah[ks][3] = *(const uint32_t*)(smc + SM_QH + o01 + 16);
        }

        float Of[8][4];
        #pragma unroll
        for (int nf = 0; nf < 8; nf++)
            #pragma unroll
            for (int r = 0; r < 4; r++) Of[nf][r] = 0.0f;
        float ds0 = 0.0f, ds1 = 0.0f;

        int row0 = qt * 128 + m0 + g;       // global (in-seq) rows of this lane
        int row1 = row0 + 8;

        for (int kt = 0; kt <= qt; kt++) {
            int p = kt & 1;

            // ---- prefetch tile kt+1 into the other buffer ----
            if (kt < qt) {
                int kb1 = b * T_ + (kt + 1) * 128;
                int q1 = (kt + 1) & 1;
                for (int idx = tid; idx < 128 * 8; idx += 512) {
                    int r = idx >> 3, c8 = (idx & 7) << 3;
                    size_t goff = (size_t)(kb1 + r) * 128 + coloff + c8;
                    uint32_t soff = (uint32_t)(r * QKP + c8) * 2;
                    CP16(KHo[q1] + soff, Kh + goff);
                    CP16(KLo[q1] + soff, Kl + goff);
                    CP16(VHo[q1] + soff, Vh + goff);
                }
                CP_COMMIT();
            }

            const char* kh_s = (const char*)smc + (KHo[p] - sb);
            const char* kl_s = (const char*)smc + (KLo[p] - sb);
            uint32_t vh_b = VHo[p];

            // ---- this warp's S-column half ----
            uint32_t Phi[4][4];

            // S = Q @ K^T (2-pass: Qh·Kh + Qh·Kl), gate, pack P frags (hi)
            #pragma unroll
            for (int jj = 0; jj < 4; jj++) {
                int jpv = 4 * sh + jj;      // PV k-step index (0..7)
                #pragma unroll
                for (int e = 0; e < 2; e++) {
                    int nfr = 2 * jpv + e;  // S n-fragment (0..15)
                    float cf[4] = {0.0f, 0.0f, 0.0f, 0.0f};
                    uint32_t kb = (uint32_t)((8 * nfr + g) * QKP + 2 * c2) * 2;
                    #pragma unroll
                    for (int ks = 0; ks < 4; ks++) {
                        uint32_t o = kb + 32 * ks;
                        uint32_t bh0 = *(const uint32_t*)(kh_s + o);
                        uint32_t bh1 = *(const uint32_t*)(kh_s + o + 16);
                        uint32_t bl0 = *(const uint32_t*)(kl_s + o);
                        uint32_t bl1 = *(const uint32_t*)(kl_s + o + 16);
                        mma16816(cf, Ah[ks], bh0, bh1);
                        mma16816(cf, Ah[ks], bl0, bl1);
                    }
                    // gate: max(silu(a),0) via tanh.approx, causal mask
                    int colb = kt * 128 + 8 * nfr + 2 * c2;
                    float g0 = 0.0f, g1 = 0.0f, g2 = 0.0f, g3 = 0.0f;
                    if (cf[0] > 0.0f && colb     <= row0) g0 = silu_fast(cf[0]);
                    if (cf[1] > 0.0f && colb + 1 <= row0) g1 = silu_fast(cf[1]);
                    if (cf[2] > 0.0f && colb     <= row1) g2 = silu_fast(cf[2]);
                    if (cf[3] > 0.0f && colb + 1 <= row1) g3 = silu_fast(cf[3]);
                    ds0 += g0 + g1;
                    ds1 += g2 + g3;
                    Phi[jj][2 * e]     = bf16x2_hi(g0, g1);
                    Phi[jj][2 * e + 1] = bf16x2_hi(g2, g3);
                }
            }

            // O += P @ V for this warp's k-half (1-pass: Phi·Vh)
            #pragma unroll
            for (int jj = 0; jj < 4; jj++) {
                int k0v = 16 * (4 * sh + jj);
                uint32_t rowa = (uint32_t)((k0v + (lane & 15)) * QKP) * 2;
                #pragma unroll
                for (int nf = 0; nf < 8; nf++) {
                    uint32_t vh0, vh1;
                    ldsm_x2_trans(vh0, vh1, vh_b + rowa + (uint32_t)(16 * nf));
                    mma16816(Of[nf], Phi[jj], vh0, vh1);
                }
            }

            CP_WAIT0();        // prefetched tile resident
            __syncthreads();   // all warps done reading buffer p
        }

        // ---- quad-reduce denominators within each warp ----
        ds0 += __shfl_xor_sync(0xffffffffu, ds0, 1);
        ds0 += __shfl_xor_sync(0xffffffffu, ds0, 2);
        ds1 += __shfl_xor_sync(0xffffffffu, ds1, 1);
        ds1 += __shfl_xor_sync(0xffffffffu, ds1, 2);

        // ---- combine the two column-half partials (scratch in K0 region) ----
        float* scr = (float*)(smc + SM_K0H + pair * 4352);
        if (sh == 1) {
            float* dst = scr + lane * 32;
            #pragma unroll
            for (int nf = 0; nf < 8; nf++) {
                dst[4 * nf + 0] = Of[nf][0];
                dst[4 * nf + 1] = Of[nf][1];
                dst[4 * nf + 2] = Of[nf][2];
                dst[4 * nf + 3] = Of[nf][3];
            }
            scr[1024 + lane * 2]     = ds0;
            scr[1024 + lane * 2 + 1] = ds1;
        }
        __syncthreads();

        if (sh == 0) {
            const float* src = scr + lane * 32;
            float dt0 = ds0 + scr[1024 + lane * 2];
            float dt1 = ds1 + scr[1024 + lane * 2 + 1];
            float f0 = (dt0 > 1e-12f) ? __fdividef(1.0f, dt0 + EPS_) : 0.0f;
            float f1 = (dt1 > 1e-12f) ? __fdividef(1.0f, dt1 + EPS_) : 0.0f;

            size_t orow0 = (size_t)(qbase + m0 + g) * 128 + coloff;
            size_t orow1 = orow0 + 8 * 128;
            #pragma unroll
            for (int nf = 0; nf < 8; nf++) {
                int c = 8 * nf + 2 * c2;
                float o0 = Of[nf][0] + src[4 * nf + 0];
                float o1 = Of[nf][1] + src[4 * nf + 1];
                float o2 = Of[nf][2] + src[4 * nf + 2];
                float o3 = Of[nf][3] + src[4 * nf + 3];
                *(float2*)(O + orow0 + c) = make_float2(o0 * f0, o1 * f0);
                *(float2*)(O + orow1 + c) = make_float2(o2 * f1, o3 * f1);
            }
        }
    }
}

// ===========================================================================
// Host orchestration
// ===========================================================================
extern "C" void kernel_launch(void* const* d_in, const int* in_sizes, int n_in,
                              void* d_out, int out_size) {
    const int*   seq    = (const int*)  d_in[0];
    // d_in[1] = attn_mask (causal tril) — synthesized in-kernel
    const float* item   = (const float*)d_in[2];
    const float* pos    = (const float*)d_in[3];
    const float* emb_s  = (const float*)d_in[4];
    const float* ln1    = (const float*)d_in[5];
    const float* Uw     = (const float*)d_in[6];
    const float* Ub     = (const float*)d_in[7];
    const float* Vw     = (const float*)d_in[8];
    const float* Vb     = (const float*)d_in[9];
    const float* Qw     = (const float*)d_in[10];
    const float* Qb     = (const float*)d_in[11];
    const float* Kw     = (const float*)d_in[12];
    const float* Kb     = (const float*)d_in[13];
    const float* f2w    = (const float*)d_in[14];
    const float* f2b    = (const float*)d_in[15];
    const float* hstu   = (const float*)d_in[16];
    const float* ln2    = (const float*)d_in[17];
    const float* c1w    = (const float*)d_in[18];
    const float* c1b    = (const float*)d_in[19];
    const float* c2w    = (const float*)d_in[20];
    const float* c2b    = (const float*)d_in[21];
    const float* last_s = (const float*)d_in[22];
    float* out = (float*)d_out;

    float *x, *u, *v, *q, *k, *av, *tb;
    cudaGetSymbolAddress((void**)&x,  g_x);
    cudaGetSymbolAddress((void**)&u,  g_u);
    cudaGetSymbolAddress((void**)&v,  g_v);
    cudaGetSymbolAddress((void**)&q,  g_q);
    cudaGetSymbolAddress((void**)&k,  g_k);
    cudaGetSymbolAddress((void**)&av, g_av);
    cudaGetSymbolAddress((void**)&tb, g_t);

    __nv_bfloat16* qh = (__nv_bfloat16*)q;
    __nv_bfloat16* kh = (__nv_bfloat16*)k;
    __nv_bfloat16* kl = kh + (size_t)BT_ * 128;
    __nv_bfloat16* vh = (__nv_bfloat16*)v;

    BfOut bfNone = {nullptr, nullptr, 1.0f};
    BfOut bfQ = {qh, nullptr, 0.125f};
    BfOut bfK = {kh, kl, 1.0f};
    BfOut bfV = {vh, nullptr, 1.0f};

    cudaFuncSetAttribute(fused_gemm,
                         cudaFuncAttributeMaxDynamicSharedMemorySize, GEMM_SMEM);
    cudaFuncSetAttribute(attn_hmma,
                         cudaFuncAttributeMaxDynamicSharedMemorySize, ATTN_SMEM);

    dim3 gemmGrid(BT_ / 128);
    dim3 attnGrid(8, B_ * H_);

    embed_rms_kernel<<<BT_ / 8, 256>>>(seq, item, pos, emb_s, x);

    for (int l = 0; l < L_; l++) {
        size_t wo = (size_t)l * D_ * D_;
        size_t bo = (size_t)l * D_;

        // QKVU: rms(x)*ln1 folded in; silu; U -> fp32, Q/V -> bf16 hi,
        // K -> bf16 hi/lo
        fused_gemm<<<gemmGrid, 512, GEMM_SMEM>>>(
            x, nullptr, ln1 + bo, 1,
            Uw + wo, Ub + bo, u,
            Vw + wo, Vb + bo, nullptr,
            Qw + wo, Qb + bo, nullptr,
            Kw + wo, Kb + bo, nullptr,
            bfNone, bfV, bfQ, bfK,
            nullptr, 4, 1);

        attn_hmma<<<attnGrid, 512, ATTN_SMEM>>>(qh, kh, kl, vh, av);

        fused_gemm<<<gemmGrid, 512, GEMM_SMEM>>>(
            av, u, hstu + bo, 1,
            f2w + wo, f2b + bo, x,
            nullptr, nullptr, nullptr,
            nullptr, nullptr, nullptr,
            nullptr, nullptr, nullptr,
            bfNone, bfNone, bfNone, bfNone,
            x, 1, 0);

        fused_gemm<<<gemmGrid, 512, GEMM_SMEM>>>(
            x, nullptr, ln2 + bo, 1,
            c1w + wo, c1b + bo, tb,
            nullptr, nullptr, nullptr,
            nullptr, nullptr, nullptr,
            nullptr, nullptr, nullptr,
            bfNone, bfNone, bfNone, bfNone,
            nullptr, 1, 2);

        fused_gemm<<<gemmGrid, 512, GEMM_SMEM>>>(
            tb, nullptr, nullptr, 0,
            c2w + wo, c2b + bo, x,
            nullptr, nullptr, nullptr,
            nullptr, nullptr, nullptr,
            nullptr, nullptr, nullptr,
            bfNone, bfNone, bfNone, bfNone,
            x, 1, 0);
    }

    rms_kernel<<<BT_ / 8, 256>>>(x, last_s, out);
}

// round 14
// speedup vs baseline: 1.7785x; 1.0533x over previous
#include <cuda_runtime.h>
#include <cuda_bf16.h>
#include <math.h>
#include <stdint.h>

// Problem constants
#define B_ 8
#define T_ 2048
#define D_ 128
#define L_ 4
#define H_ 2
#define HD_ 64
#define BT_ (B_ * T_)          // 16384 rows
#define EPS_ 1e-8f

#define GP 132                 // smem pitch (floats) for 128-wide gemm tiles
#define GEMM_SMEM ((2 * 128 * GP + 128) * 4)

// ---------------------------------------------------------------------------
// Scratch buffers (allocation-free: __device__ globals)
// ---------------------------------------------------------------------------
__device__ float g_x [BT_ * D_];
__device__ float g_u [BT_ * D_];
__device__ float g_v [BT_ * D_];   // vh
__device__ float g_q [BT_ * D_];   // qh
__device__ float g_k [BT_ * D_];   // kh
__device__ float g_av[BT_ * D_];
__device__ float g_t [BT_ * D_];

// bf16 output descriptor for fused_gemm (hi only when lo == nullptr)
struct BfOut {
    __nv_bfloat16* hi;
    __nv_bfloat16* lo;
    float scale;
};

// ===========================================================================
// Small helpers
// ===========================================================================
__device__ __forceinline__ uint32_t smem_u32(const void* p) {
    uint32_t a;
    asm("{ .reg .u64 t; cvta.to.shared.u64 t, %1; cvt.u32.u64 %0, t; }"
        : "=r"(a) : "l"(p));
    return a;
}

#define CP16(saddr, gptr) \
    asm volatile("cp.async.cg.shared.global [%0], [%1], 16;" \
                 :: "r"((uint32_t)(saddr)), "l"(gptr) : "memory")
#define CP_COMMIT() asm volatile("cp.async.commit_group;" ::: "memory")
#define CP_WAIT0()  asm volatile("cp.async.wait_group 0;" ::: "memory")

__device__ __forceinline__ float tanh_approx(float x) {
    float r;
    asm("tanh.approx.f32 %0, %1;" : "=f"(r) : "f"(x));
    return r;
}

// silu via single-MUFU tanh; for a >= 0 equals max(silu(a),0)
__device__ __forceinline__ float silu_fast(float a) {
    return a * 0.5f * (1.0f + tanh_approx(0.5f * a));
}

// bf16 hi/lo split of an fp32 value
__device__ __forceinline__ void split_bf16(float x, __nv_bfloat16& h, __nv_bfloat16& l) {
    h = __float2bfloat16(x);
    l = __float2bfloat16(x - __bfloat162float(h));
}

__device__ __forceinline__ uint32_t bf16x2_hi(float x, float y) {
    __nv_bfloat162 t = __floats2bfloat162_rn(x, y);  // .x = x in low half
    return *reinterpret_cast<uint32_t*>(&t);
}

// mma.sync m16n8k16 bf16 -> f32 (accumulate in place)
__device__ __forceinline__ void mma16816(float* c, const uint32_t* a,
                                         uint32_t b0, uint32_t b1) {
    asm volatile(
        "mma.sync.aligned.m16n8k16.row.col.f32.bf16.bf16.f32 "
        "{%0,%1,%2,%3}, {%4,%5,%6,%7}, {%8,%9}, {%0,%1,%2,%3};"
        : "+f"(c[0]), "+f"(c[1]), "+f"(c[2]), "+f"(c[3])
        : "r"(a[0]), "r"(a[1]), "r"(a[2]), "r"(a[3]), "r"(b0), "r"(b1));
}

// ldmatrix x4 (non-transposed): 4 8x8 b16 matrices
__device__ __forceinline__ void ldsm_x4(uint32_t& r0, uint32_t& r1,
                                        uint32_t& r2, uint32_t& r3, uint32_t addr) {
    asm volatile("ldmatrix.sync.aligned.m8n8.x4.shared.b16 {%0,%1,%2,%3}, [%4];"
                 : "=r"(r0), "=r"(r1), "=r"(r2), "=r"(r3) : "r"(addr));
}

// ldmatrix x2 transposed (for V B-fragments from row-major V[key][d])
__device__ __forceinline__ void ldsm_x2_trans(uint32_t& r0, uint32_t& r1, uint32_t addr) {
    asm volatile("ldmatrix.sync.aligned.m8n8.x2.trans.shared.b16 {%0,%1}, [%2];"
                 : "=r"(r0), "=r"(r1) : "r"(addr));
}

// ===========================================================================
// Elementwise RMS kernels
// ===========================================================================
__global__ void rms_kernel(const float* __restrict__ in,
                           const float* __restrict__ sc,
                           float* __restrict__ out) {
    int warp = threadIdx.x >> 5, lane = threadIdx.x & 31;
    size_t row = (size_t)blockIdx.x * 8 + warp;
    float4 v = *(const float4*)(in + row * 128 + lane * 4);
    float ss = v.x * v.x + v.y * v.y + v.z * v.z + v.w * v.w;
    #pragma unroll
    for (int o = 16; o > 0; o >>= 1) ss += __shfl_xor_sync(0xffffffffu, ss, o);
    float r = rsqrtf(ss * (1.0f / 128.0f) + EPS_);
    float4 s = *(const float4*)(sc + lane * 4);
    *(float4*)(out + row * 128 + lane * 4) =
        make_float4(v.x * r * s.x, v.y * r * s.y, v.z * r * s.z, v.w * r * s.w);
}

__global__ void embed_rms_kernel(const int* __restrict__ seq,
                                 const float* __restrict__ item,
                                 const float* __restrict__ pos,
                                 const float* __restrict__ sc,
                                 float* __restrict__ out) {
    int warp = threadIdx.x >> 5, lane = threadIdx.x & 31;
    size_t row = (size_t)blockIdx.x * 8 + warp;
    int t = (int)(row & (T_ - 1));
    int id = seq[row];
    float4 a = *(const float4*)(item + (size_t)id * 128 + lane * 4);
    float4 p = *(const float4*)(pos + (size_t)(t + 1) * 128 + lane * 4);
    float4 v = make_float4(a.x + p.x, a.y + p.y, a.z + p.z, a.w + p.w);
    float ss = v.x * v.x + v.y * v.y + v.z * v.z + v.w * v.w;
    #pragma unroll
    for (int o = 16; o > 0; o >>= 1) ss += __shfl_xor_sync(0xffffffffu, ss, o);
    float r = rsqrtf(ss * (1.0f / 128.0f) + EPS_);
    float4 s = *(const float4*)(sc + lane * 4);
    *(float4*)(out + row * 128 + lane * 4) =
        make_float4(v.x * r * s.x, v.y * r * s.y, v.z * r * s.z, v.w * r * s.w);
}

// ===========================================================================
// Fused GEMM (fp32 SIMT), 512 threads, 4x8 outputs/thread.
// ===========================================================================
__global__ void __launch_bounds__(512)
fused_gemm(const float* __restrict__ A,
           const float* __restrict__ mul,
           const float* __restrict__ scvec,
           int use_rms,
           const float* __restrict__ W0, const float* __restrict__ B0, float* __restrict__ O0,
           const float* __restrict__ W1, const float* __restrict__ B1, float* __restrict__ O1,
           const float* __restrict__ W2, const float* __restrict__ B2, float* __restrict__ O2,
           const float* __restrict__ W3, const float* __restrict__ B3, float* __restrict__ O3,
           BfOut bf0, BfOut bf1, BfOut bf2, BfOut bf3,
           const float* __restrict__ res,
           int nw, int act) {
    extern __shared__ float sm[];
    float* As = sm;
    float* Ws = As + 128 * GP;
    float* rr = Ws + 128 * GP;

    int tid = threadIdx.x;
    int row0 = blockIdx.x * 128;

    for (int idx = tid; idx < 128 * 32; idx += 512) {
        int r = idx >> 5, c4 = (idx & 31) << 2;
        *(float4*)(As + r * GP + c4) =
            *(const float4*)(A + (size_t)(row0 + r) * 128 + c4);
    }
    __syncthreads();

    if (use_rms) {
        int w = tid >> 5, lane = tid & 31;
        for (int r = w; r < 128; r += 16) {
            float4 v = *(const float4*)(As + r * GP + lane * 4);
            float ss = v.x * v.x + v.y * v.y + v.z * v.z + v.w * v.w;
            #pragma unroll
            for (int off = 16; off > 0; off >>= 1)
                ss += __shfl_xor_sync(0xffffffffu, ss, off);
            if (lane == 0) rr[r] = rsqrtf(ss * (1.0f / 128.0f) + EPS_);
        }
    } else {
        if (tid < 128) rr[tid] = 1.0f;
    }
    __syncthreads();

    if (mul) {
        for (int idx = tid; idx < 128 * 32; idx += 512) {
            int r = idx >> 5, c4 = (idx & 31) << 2;
            float4 m = *(const float4*)(mul + (size_t)(row0 + r) * 128 + c4);
            float4 a = *(float4*)(As + r * GP + c4);
            a.x *= m.x; a.y *= m.y; a.z *= m.z; a.w *= m.w;
            *(float4*)(As + r * GP + c4) = a;
        }
    }

    int ti = tid >> 4, tj = tid & 15;
    int r0 = ti * 4, c0 = tj * 8;

    const float* Wp[4] = {W0, W1, W2, W3};
    const float* Bp[4] = {B0, B1, B2, B3};
    float*       Op[4] = {O0, O1, O2, O3};
    BfOut        Bf[4] = {bf0, bf1, bf2, bf3};

    for (int wi = 0; wi < nw; wi++) {
        const float* W = Wp[wi];
        for (int idx = tid; idx < 128 * 32; idx += 512) {
            int r = idx >> 5, c4 = (idx & 31) << 2;
            float s = scvec ? scvec[r] : 1.0f;
            float4 v = *(const float4*)(W + (size_t)r * 128 + c4);
            v.x *= s; v.y *= s; v.z *= s; v.w *= s;
            *(float4*)(Ws + r * GP + c4) = v;
        }
        __syncthreads();

        float acc[4][8];
        #pragma unroll
        for (int i = 0; i < 4; i++)
            #pragma unroll
            for (int j = 0; j < 8; j++) acc[i][j] = 0.0f;

        for (int k = 0; k < 128; k += 4) {
            float4 w0[4], w1[4];
            #pragma unroll
            for (int kk = 0; kk < 4; kk++) {
                w0[kk] = *(const float4*)(Ws + (k + kk) * GP + c0);
                w1[kk] = *(const float4*)(Ws + (k + kk) * GP + c0 + 4);
            }
            #pragma unroll
            for (int i = 0; i < 4; i++) {
                float4 a = *(const float4*)(As + (r0 + i) * GP + k);
                acc[i][0] += a.x * w0[0].x + a.y * w0[1].x + a.z * w0[2].x + a.w * w0[3].x;
                acc[i][1] += a.x * w0[0].y + a.y * w0[1].y + a.z * w0[2].y + a.w * w0[3].y;
                acc[i][2] += a.x * w0[0].z + a.y * w0[1].z + a.z * w0[2].z + a.w * w0[3].z;
                acc[i][3] += a.x * w0[0].w + a.y * w0[1].w + a.z * w0[2].w + a.w * w0[3].w;
                acc[i][4] += a.x * w1[0].x + a.y * w1[1].x + a.z * w1[2].x + a.w * w1[3].x;
                acc[i][5] += a.x * w1[0].y + a.y * w1[1].y + a.z * w1[2].y + a.w * w1[3].y;
                acc[i][6] += a.x * w1[0].z + a.y * w1[1].z + a.z * w1[2].z + a.w * w1[3].z;
                acc[i][7] += a.x * w1[0].w + a.y * w1[1].w + a.z * w1[2].w + a.w * w1[3].w;
            }
        }

        const float* Bv = Bp[wi];
        float* Ov = Op[wi];
        BfOut bfo = Bf[wi];
        #pragma unroll
        for (int i = 0; i < 4; i++) {
            float rri = rr[r0 + i];
            size_t grow = (size_t)(row0 + r0 + i) * 128;
            float vout[8];
            #pragma unroll
            for (int j = 0; j < 8; j++) {
                float v = acc[i][j] * rri + Bv[c0 + j];
                if (act == 1) {
                    v = v * __fdividef(1.0f, 1.0f + __expf(-v));
                } else if (act == 2) {
                    v = 0.5f * v * (1.0f + erff(v * 0.70710678118654752f));
                }
                vout[j] = v;
            }
            if (bfo.hi) {
                if (bfo.lo) {
                    __nv_bfloat16 hh[8], ll[8];
                    #pragma unroll
                    for (int j = 0; j < 8; j++)
                        split_bf16(vout[j] * bfo.scale, hh[j], ll[j]);
                    *(uint4*)(bfo.hi + grow + c0) = *(const uint4*)hh;
                    *(uint4*)(bfo.lo + grow + c0) = *(const uint4*)ll;
                } else {
                    __nv_bfloat16 hh[8];
                    #pragma unroll
                    for (int j = 0; j < 8; j++)
                        hh[j] = __float2bfloat16(vout[j] * bfo.scale);
                    *(uint4*)(bfo.hi + grow + c0) = *(const uint4*)hh;
                }
            } else {
                if (res) {
                    #pragma unroll
                    for (int j = 0; j < 8; j++) vout[j] += res[grow + c0 + j];
                }
                *(float4*)(Ov + grow + c0)     = make_float4(vout[0], vout[1], vout[2], vout[3]);
                *(float4*)(Ov + grow + c0 + 4) = make_float4(vout[4], vout[5], vout[6], vout[7]);
            }
        }
        __syncthreads();
    }
}

// ===========================================================================
// HMMA HSTU attention, double-buffered cp.async pipeline.
// QK: 1-pass (Qh·Kh, ldmatrix.x4 fragment loads). PV: 1-pass (Phi·Vh).
// Gate: branch-free silu_fast(fmax(a,0)) with diag-only causal zeroing.
// grid = (8, 16), block = 512. Warp pair (2p,2p+1) owns rows [16p,16p+16);
// warps split S-cols (sh). Block handles q-tiles qp and 15-qp.
// ===========================================================================
#define QKP 72                 // row pitch in bf16 elements (144B)
#define TILEB 18432            // one 128 x QKP bf16 tile
#define SM_QH  0
#define SM_K0H (1 * TILEB)     // buf0 K (reused as combine scratch at end)
#define SM_V0H (2 * TILEB)
#define SM_K1H (3 * TILEB)
#define SM_V1H (4 * TILEB)
#define ATTN_SMEM (5 * TILEB)   // 92160 bytes

__global__ void __launch_bounds__(512, 1)
attn_hmma(const __nv_bfloat16* __restrict__ Qh,
          const __nv_bfloat16* __restrict__ Kh,
          const __nv_bfloat16* __restrict__ Vh,
          float* __restrict__ O) {
    extern __shared__ char smc[];
    uint32_t sb = smem_u32(smc);

    int tid  = threadIdx.x;
    int warp = tid >> 5;       // 0..15
    int lane = tid & 31;
    int pair = warp >> 1;      // 0..7
    int sh   = warp & 1;       // column half
    int g    = lane >> 2;      // fragment group row 0..7
    int c2   = lane & 3;       // fragment group col 0..3
    int m0   = pair * 16;      // pair's S/O row base (0..112)

    int bh = blockIdx.y;
    int b = bh >> 1, h = bh & 1;
    int coloff = h * HD_;
    int qp = blockIdx.x;

    const uint32_t KHo[2] = {sb + SM_K0H, sb + SM_K1H};
    const uint32_t VHo[2] = {sb + SM_V0H, sb + SM_V1H};

    // per-lane ldmatrix base offset for K fragments:
    // lanes 0..7 -> rows, matrix m = lane>>3 selects +8-col steps
    uint32_t kfrag_lane = (uint32_t)(((lane & 7) * QKP + 8 * (lane >> 3)) * 2);

    for (int half = 0; half < 2; half++) {
        int qt = half ? (15 - qp) : qp;
        int qbase = b * T_ + qt * 128;

        __syncthreads();   // previous q-tile consumers / scratch users done

        // ---- async copy: Q tile + K/V tile 0 ----
        for (int idx = tid; idx < 128 * 8; idx += 512) {
            int r = idx >> 3, c8 = (idx & 7) << 3;
            size_t goff = (size_t)(qbase + r) * 128 + coloff + c8;
            uint32_t soff = (uint32_t)(r * QKP + c8) * 2;
            CP16(sb + SM_QH + soff, Qh + goff);
        }
        {
            int kbase0 = b * T_;   // kt = 0
            for (int idx = tid; idx < 128 * 8; idx += 512) {
                int r = idx >> 3, c8 = (idx & 7) << 3;
                size_t goff = (size_t)(kbase0 + r) * 128 + coloff + c8;
                uint32_t soff = (uint32_t)(r * QKP + c8) * 2;
                CP16(KHo[0] + soff, Kh + goff);
                CP16(VHo[0] + soff, Vh + goff);
            }
        }
        CP_COMMIT();
        CP_WAIT0();
        __syncthreads();

        // ---- A fragments for this pair's 16 Q rows ----
        uint32_t Ah[4][4];
        #pragma unroll
        for (int ks = 0; ks < 4; ks++) {
            uint32_t o00 = (uint32_t)((m0 + g)     * QKP + 16 * ks + 2 * c2) * 2;
            uint32_t o01 = (uint32_t)((m0 + g + 8) * QKP + 16 * ks + 2 * c2) * 2;
            Ah[ks][0] = *(const uint32_t*)(smc + SM_QH + o00);
            Ah[ks][1] = *(const uint32_t*)(smc + SM_QH + o01);
            Ah[ks][2] = *(const uint32_t*)(smc + SM_QH + o00 + 16);
            Ah[ks][3] = *(const uint32_t*)(smc + SM_QH + o01 + 16);
        }

        float Of[8][4];
        #pragma unroll
        for (int nf = 0; nf < 8; nf++)
            #pragma unroll
            for (int r = 0; r < 4; r++) Of[nf][r] = 0.0f;
        float ds0 = 0.0f, ds1 = 0.0f;

        int row0 = qt * 128 + m0 + g;       // global (in-seq) rows of this lane
        int row1 = row0 + 8;

        for (int kt = 0; kt <= qt; kt++) {
            int p = kt & 1;
            bool diag = (kt == qt);

            // ---- prefetch tile kt+1 into the other buffer ----
            if (kt < qt) {
                int kb1 = b * T_ + (kt + 1) * 128;
                int q1 = (kt + 1) & 1;
                for (int idx = tid; idx < 128 * 8; idx += 512) {
                    int r = idx >> 3, c8 = (idx & 7) << 3;
                    size_t goff = (size_t)(kb1 + r) * 128 + coloff + c8;
                    uint32_t soff = (uint32_t)(r * QKP + c8) * 2;
                    CP16(KHo[q1] + soff, Kh + goff);
                    CP16(VHo[q1] + soff, Vh + goff);
                }
                CP_COMMIT();
            }

            uint32_t kh_b = KHo[p] + kfrag_lane;
            uint32_t vh_b = VHo[p];

            // ---- this warp's S-column half ----
            uint32_t Phi[4][4];

            #pragma unroll
            for (int jj = 0; jj < 4; jj++) {
                int jpv = 4 * sh + jj;      // PV k-step index (0..7)
                #pragma unroll
                for (int e = 0; e < 2; e++) {
                    int nfr = 2 * jpv + e;  // S n-fragment (0..15)
                    float cf[4] = {0.0f, 0.0f, 0.0f, 0.0f};
                    uint32_t kb = kh_b + (uint32_t)(nfr * 8 * QKP * 2);
                    // two ldmatrix.x4: ks 0,1 then ks 2,3
                    uint32_t b0, b1, b2, b3;
                    ldsm_x4(b0, b1, b2, b3, kb);
                    mma16816(cf, Ah[0], b0, b1);
                    mma16816(cf, Ah[1], b2, b3);
                    ldsm_x4(b0, b1, b2, b3, kb + 64);
                    mma16816(cf, Ah[2], b0, b1);
                    mma16816(cf, Ah[3], b2, b3);

                    // gate: silu_fast(max(a,0)) ; causal zeroing on diag tile
                    float a0 = fmaxf(cf[0], 0.0f);
                    float a1 = fmaxf(cf[1], 0.0f);
                    float a2 = fmaxf(cf[2], 0.0f);
                    float a3 = fmaxf(cf[3], 0.0f);
                    if (diag) {
                        int colb = kt * 128 + 8 * nfr + 2 * c2;
                        if (colb     > row0) a0 = 0.0f;
                        if (colb + 1 > row0) a1 = 0.0f;
                        if (colb     > row1) a2 = 0.0f;
                        if (colb + 1 > row1) a3 = 0.0f;
                    }
                    float g0 = silu_fast(a0);
                    float g1 = silu_fast(a1);
                    float g2 = silu_fast(a2);
                    float g3 = silu_fast(a3);
                    ds0 += g0 + g1;
                    ds1 += g2 + g3;
                    Phi[jj][2 * e]     = bf16x2_hi(g0, g1);
                    Phi[jj][2 * e + 1] = bf16x2_hi(g2, g3);
                }
            }

            // O += P @ V for this warp's k-half (1-pass: Phi·Vh)
            #pragma unroll
            for (int jj = 0; jj < 4; jj++) {
                int k0v = 16 * (4 * sh + jj);
                uint32_t rowa = (uint32_t)((k0v + (lane & 15)) * QKP) * 2;
                #pragma unroll
                for (int nf = 0; nf < 8; nf++) {
                    uint32_t vh0, vh1;
                    ldsm_x2_trans(vh0, vh1, vh_b + rowa + (uint32_t)(16 * nf));
                    mma16816(Of[nf], Phi[jj], vh0, vh1);
                }
            }

            CP_WAIT0();        // prefetched tile resident
            __syncthreads();   // all warps done reading buffer p
        }

        // ---- quad-reduce denominators within each warp ----
        ds0 += __shfl_xor_sync(0xffffffffu, ds0, 1);
        ds0 += __shfl_xor_sync(0xffffffffu, ds0, 2);
        ds1 += __shfl_xor_sync(0xffffffffu, ds1, 1);
        ds1 += __shfl_xor_sync(0xffffffffu, ds1, 2);

        // ---- combine the two column-half partials (scratch in K0/V0 region) ----
        float* scr = (float*)(smc + SM_K0H + pair * 4352);
        if (sh == 1) {
            float* dst = scr + lane * 32;
            #pragma unroll
            for (int nf = 0; nf < 8; nf++) {
                dst[4 * nf + 0] = Of[nf][0];
                dst[4 * nf + 1] = Of[nf][1];
                dst[4 * nf + 2] = Of[nf][2];
                dst[4 * nf + 3] = Of[nf][3];
            }
            scr[1024 + lane * 2]     = ds0;
            scr[1024 + lane * 2 + 1] = ds1;
        }
        __syncthreads();

        if (sh == 0) {
            const float* src = scr + lane * 32;
            float dt0 = ds0 + scr[1024 + lane * 2];
            float dt1 = ds1 + scr[1024 + lane * 2 + 1];
            float f0 = (dt0 > 1e-12f) ? __fdividef(1.0f, dt0 + EPS_) : 0.0f;
            float f1 = (dt1 > 1e-12f) ? __fdividef(1.0f, dt1 + EPS_) : 0.0f;

            size_t orow0 = (size_t)(qbase + m0 + g) * 128 + coloff;
            size_t orow1 = orow0 + 8 * 128;
            #pragma unroll
            for (int nf = 0; nf < 8; nf++) {
                int c = 8 * nf + 2 * c2;
                float o0 = Of[nf][0] + src[4 * nf + 0];
                float o1 = Of[nf][1] + src[4 * nf + 1];
                float o2 = Of[nf][2] + src[4 * nf + 2];
                float o3 = Of[nf][3] + src[4 * nf + 3];
                *(float2*)(O + orow0 + c) = make_float2(o0 * f0, o1 * f0);
                *(float2*)(O + orow1 + c) = make_float2(o2 * f1, o3 * f1);
            }
        }
    }
}

// ===========================================================================
// Host orchestration
// ===========================================================================
extern "C" void kernel_launch(void* const* d_in, const int* in_sizes, int n_in,
                              void* d_out, int out_size) {
    const int*   seq    = (const int*)  d_in[0];
    // d_in[1] = attn_mask (causal tril) — synthesized in-kernel
    const float* item   = (const float*)d_in[2];
    const float* pos    = (const float*)d_in[3];
    const float* emb_s  = (const float*)d_in[4];
    const float* ln1    = (const float*)d_in[5];
    const float* Uw     = (const float*)d_in[6];
    const float* Ub     = (const float*)d_in[7];
    const float* Vw     = (const float*)d_in[8];
    const float* Vb     = (const float*)d_in[9];
    const float* Qw     = (const float*)d_in[10];
    const float* Qb     = (const float*)d_in[11];
    const float* Kw     = (const float*)d_in[12];
    const float* Kb     = (const float*)d_in[13];
    const float* f2w    = (const float*)d_in[14];
    const float* f2b    = (const float*)d_in[15];
    const float* hstu   = (const float*)d_in[16];
    const float* ln2    = (const float*)d_in[17];
    const float* c1w    = (const float*)d_in[18];
    const float* c1b    = (const float*)d_in[19];
    const float* c2w    = (const float*)d_in[20];
    const float* c2b    = (const float*)d_in[21];
    const float* last_s = (const float*)d_in[22];
    float* out = (float*)d_out;

    float *x, *u, *v, *q, *k, *av, *tb;
    cudaGetSymbolAddress((void**)&x,  g_x);
    cudaGetSymbolAddress((void**)&u,  g_u);
    cudaGetSymbolAddress((void**)&v,  g_v);
    cudaGetSymbolAddress((void**)&q,  g_q);
    cudaGetSymbolAddress((void**)&k,  g_k);
    cudaGetSymbolAddress((void**)&av, g_av);
    cudaGetSymbolAddress((void**)&tb, g_t);

    __nv_bfloat16* qh = (__nv_bfloat16*)q;
    __nv_bfloat16* kh = (__nv_bfloat16*)k;
    __nv_bfloat16* vh = (__nv_bfloat16*)v;

    BfOut bfNone = {nullptr, nullptr, 1.0f};
    BfOut bfQ = {qh, nullptr, 0.125f};
    BfOut bfK = {kh, nullptr, 1.0f};
    BfOut bfV = {vh, nullptr, 1.0f};

    cudaFuncSetAttribute(fused_gemm,
                         cudaFuncAttributeMaxDynamicSharedMemorySize, GEMM_SMEM);
    cudaFuncSetAttribute(attn_hmma,
                         cudaFuncAttributeMaxDynamicSharedMemorySize, ATTN_SMEM);

    dim3 gemmGrid(BT_ / 128);
    dim3 attnGrid(8, B_ * H_);

    embed_rms_kernel<<<BT_ / 8, 256>>>(seq, item, pos, emb_s, x);

    for (int l = 0; l < L_; l++) {
        size_t wo = (size_t)l * D_ * D_;
        size_t bo = (size_t)l * D_;

        // QKVU: rms(x)*ln1 folded in; silu; U -> fp32, Q/K/V -> bf16 hi
        fused_gemm<<<gemmGrid, 512, GEMM_SMEM>>>(
            x, nullptr, ln1 + bo, 1,
            Uw + wo, Ub + bo, u,
            Vw + wo, Vb + bo, nullptr,
            Qw + wo, Qb + bo, nullptr,
            Kw + wo, Kb + bo, nullptr,
            bfNone, bfV, bfQ, bfK,
            nullptr, 4, 1);

        attn_hmma<<<attnGrid, 512, ATTN_SMEM>>>(qh, kh, vh, av);

        fused_gemm<<<gemmGrid, 512, GEMM_SMEM>>>(
            av, u, hstu + bo, 1,
            f2w + wo, f2b + bo, x,
            nullptr, nullptr, nullptr,
            nullptr, nullptr, nullptr,
            nullptr, nullptr, nullptr,
            bfNone, bfNone, bfNone, bfNone,
            x, 1, 0);

        fused_gemm<<<gemmGrid, 512, GEMM_SMEM>>>(
            x, nullptr, ln2 + bo, 1,
            c1w + wo, c1b + bo, tb,
            nullptr, nullptr, nullptr,
            nullptr, nullptr, nullptr,
            nullptr, nullptr, nullptr,
            bfNone, bfNone, bfNone, bfNone,
            nullptr, 1, 2);

        fused_gemm<<<gemmGrid, 512, GEMM_SMEM>>>(
            tb, nullptr, nullptr, 0,
            c2w + wo, c2b + bo, x,
            nullptr, nullptr, nullptr,
            nullptr, nullptr, nullptr,
            nullptr, nullptr, nullptr,
            bfNone, bfNone, bfNone, bfNone,
            x, 1, 0);
    }

    rms_kernel<<<BT_ / 8, 256>>>(x, last_s, out);
}